// round 1
// baseline (speedup 1.0000x reference)
#include <cuda_runtime.h>

#define BB 128
#define TE 512
#define TD 128
#define EHD 512
#define DHD 512
#define KC 7
#define CC 105
#define KW 617   // CC + DHD

// ---------------- scratch (device globals; no allocations allowed) -----------
__device__ float g_phi[TE * EHD];          // phi[t][e]
__device__ float g_Wa[BB * TD];            // Wa + Wa_b
__device__ float g_sh[BB * 4 * DHD];       // s_i@Whh.T + bhh + bih
__device__ float g_sdot[BB * KC];          // s_i@w_s.T + wij_b
__device__ float g_cp[BB * CC];            // c_p
__device__ float g_E[BB * TD * TE];        // scores -> softmax in place
__device__ float g_ci[BB * TD * EHD];      // attention output

__device__ __forceinline__ float sigm(float x) { return 1.f / (1.f + __expf(-x)); }

// ---------------- K1: phi[t][e] = phi_b[e] + sum_{t'<t} phi_w[e][t'] ---------
__global__ void k_phi(const float* __restrict__ phi_w, const float* __restrict__ phi_b) {
    int e = blockIdx.x, t = threadIdx.x;
    __shared__ float s[2][TE];
    s[0][t] = phi_w[e * TE + t];
    __syncthreads();
    int src = 0;
    for (int off = 1; off < TE; off <<= 1) {
        float v = s[src][t];
        if (t >= off) v += s[src][t - off];
        s[src ^ 1][t] = v;
        __syncthreads();
        src ^= 1;
    }
    g_phi[t * EHD + e] = phi_b[e] + (t ? s[src][t - 1] : 0.f);
}

// ---------------- K2: fused small GEMM: C = s_i @ W.T for [Wa_w; Whh; w_s] ---
#define N2 2183   // 128 + 2048 + 7
__global__ void k_prep(const float* __restrict__ s_i,
                       const float* __restrict__ Wa_w, const float* __restrict__ Wa_b,
                       const float* __restrict__ Whh,  const float* __restrict__ bhh,
                       const float* __restrict__ bih,
                       const float* __restrict__ wij_w, const float* __restrict__ wij_b) {
    __shared__ float As[128][33];
    __shared__ float Ws[64][33];
    int tid = threadIdx.x;
    int tx = tid & 15, ty = tid >> 4;
    int n0 = blockIdx.x * 64;
    float acc[8][4];
#pragma unroll
    for (int a = 0; a < 8; a++)
#pragma unroll
        for (int c = 0; c < 4; c++) acc[a][c] = 0.f;

    for (int k0 = 0; k0 < DHD; k0 += 32) {
#pragma unroll
        for (int r = 0; r < 16; r++) {
            int lin = tid + 256 * r;
            int row = lin >> 5, kk = lin & 31;
            As[row][kk] = s_i[row * DHD + k0 + kk];
        }
#pragma unroll
        for (int r = 0; r < 8; r++) {
            int lin = tid + 256 * r;
            int col = lin >> 5, kk = lin & 31;
            int n = n0 + col, k = k0 + kk;
            float v = 0.f;
            if (n < TD)                 v = Wa_w[n * DHD + k];
            else if (n < TD + 4 * DHD)  v = Whh[(n - TD) * DHD + k];
            else if (n < N2)            v = wij_w[(n - TD - 4 * DHD) * KW + CC + k];
            Ws[col][kk] = v;
        }
        __syncthreads();
#pragma unroll
        for (int kk = 0; kk < 32; kk++) {
            float xv[8], wv[4];
#pragma unroll
            for (int jm = 0; jm < 8; jm++) xv[jm] = As[ty + 16 * jm][kk];
#pragma unroll
            for (int jn = 0; jn < 4; jn++) wv[jn] = Ws[tx + 16 * jn][kk];
#pragma unroll
            for (int jm = 0; jm < 8; jm++)
#pragma unroll
                for (int jn = 0; jn < 4; jn++) acc[jm][jn] += xv[jm] * wv[jn];
        }
        __syncthreads();
    }
#pragma unroll
    for (int jm = 0; jm < 8; jm++) {
        int m = ty + 16 * jm;
#pragma unroll
        for (int jn = 0; jn < 4; jn++) {
            int n = n0 + tx + 16 * jn;
            float v = acc[jm][jn];
            if (n < TD)                g_Wa[m * TD + n] = v + Wa_b[n];
            else if (n < TD + 4 * DHD) g_sh[m * 4 * DHD + (n - TD)] = v + bhh[n - TD] + bih[n - TD];
            else if (n < N2)           g_sdot[m * KC + (n - TD - 4 * DHD)] = v + wij_b[n - TD - 4 * DHD];
        }
    }
}

// ---------------- K3: CNN path: ep, global-scalar-normalized ap, c_p ---------
__global__ void k_cnn(const float* __restrict__ CNNs, const float* __restrict__ wij_w) {
    __shared__ float ep_s[BB * KC];
    __shared__ float red[32];
    __shared__ float Ssh;
    int tid = threadIdx.x;     // 896 threads, one per (b,k)
    int k = tid % KC;
    float acc = g_sdot[tid];
    const float* crow = CNNs + tid * CC;
    const float* wrow = wij_w + k * KW;
#pragma unroll 5
    for (int c = 0; c < CC; c++) acc += crow[c] * wrow[c];
    float epv = tanhf(acc);

    float v = epv;
#pragma unroll
    for (int o = 16; o; o >>= 1) v += __shfl_xor_sync(0xffffffffu, v, o);
    if ((tid & 31) == 0) red[tid >> 5] = v;
    __syncthreads();
    if (tid == 0) {
        float s = 0.f;
        for (int w = 0; w < 28; w++) s += red[w];
        Ssh = s;            // NOTE: reference divides by sum of ep (not exp(ep))
    }
    __syncthreads();
    ep_s[tid] = __expf(epv) / Ssh;
    __syncthreads();
    for (int o = tid; o < BB * CC; o += 896) {
        int b = o / CC, c = o % CC;
        float s = 0.f;
#pragma unroll
        for (int kk = 0; kk < KC; kk++)
            s += ep_s[b * KC + kk] * CNNs[(b * KC + kk) * CC + c];
        g_cp[o] = s;
    }
}

// ---------------- K4: banded score GEMM + tanh/va assembly -------------------
// e[b,i,t] = tanh(Ua[b,t,s]+Ua_b[s])*va[s+128]+vb   (s = i+384-t >= 0)
//          = tanh(Wa[b,j])*va[j]+vb                 (j = i+512-t < 128 otherwise)
__global__ void k_escore(const float* __restrict__ LSTM, const float* __restrict__ Ua_w,
                         const float* __restrict__ Ua_b, const float* __restrict__ va_w,
                         const float* __restrict__ va_b) {
    __shared__ float Us[192][33];   // Ua_w rows s = s_lo + r (zero-filled OOB)
    __shared__ float Ps[64][33];    // phi*LSTM tile over t
    int tid = threadIdx.x;
    int tx = tid & 15, ty = tid >> 4;   // tx -> t lanes (write coalescing), ty -> i
    int t0 = blockIdx.x * 64;
    int b = blockIdx.y;
    int s_lo = 321 - t0;                // = 384 - (t0+63)
    const float* Lb = LSTM + b * TE * EHD;
    float acc[4][8];
#pragma unroll
    for (int a = 0; a < 4; a++)
#pragma unroll
        for (int c = 0; c < 8; c++) acc[a][c] = 0.f;

    for (int k0 = 0; k0 < EHD; k0 += 32) {
#pragma unroll
        for (int r = 0; r < 24; r++) {
            int lin = tid + 256 * r;
            int row = lin >> 5, kk = lin & 31;
            int s = s_lo + row;
            Us[row][kk] = ((unsigned)s < 512u) ? Ua_w[s * EHD + k0 + kk] : 0.f;
        }
#pragma unroll
        for (int r = 0; r < 8; r++) {
            int lin = tid + 256 * r;
            int row = lin >> 5, kk = lin & 31;
            int t = t0 + row;
            Ps[row][kk] = g_phi[t * EHD + k0 + kk] * Lb[t * EHD + k0 + kk];
        }
        __syncthreads();
        int base2 = 15 + ty - tx;   // row = base2 + 16*di, di = (ii-tt)+3
#pragma unroll
        for (int kk = 0; kk < 32; kk++) {
            float p[4], u[11];
#pragma unroll
            for (int tt = 0; tt < 4; tt++) p[tt] = Ps[tx + 16 * tt][kk];
#pragma unroll
            for (int di = 0; di < 11; di++) u[di] = Us[base2 + 16 * di][kk];
#pragma unroll
            for (int tt = 0; tt < 4; tt++)
#pragma unroll
                for (int ii = 0; ii < 8; ii++)
                    acc[tt][ii] += p[tt] * u[ii - tt + 3];
        }
        __syncthreads();
    }
    float vb = va_b[0];
#pragma unroll
    for (int tt = 0; tt < 4; tt++) {
        int t = t0 + tx + 16 * tt;
#pragma unroll
        for (int ii = 0; ii < 8; ii++) {
            int i = ty + 16 * ii;
            int s = i + 384 - t;
            int jc = s + 128;              // = i + 512 - t, index into va_w (len 640)
            float ev;
            if (s >= 0) ev = tanhf(acc[tt][ii] + Ua_b[s]) * va_w[jc] + vb;
            else        ev = tanhf(g_Wa[b * TD + jc]) * va_w[jc] + vb;
            g_E[(b * TD + i) * TE + t] = ev;
        }
    }
}

// ---------------- K5: row softmax over t (in place on g_E) -------------------
__global__ void k_softmax() {
    int row = blockIdx.x;
    float* p = g_E + row * TE;
    int tid = threadIdx.x;   // 256
    __shared__ float red[8], red2[8];
    float v0 = p[tid], v1 = p[tid + 256];
    float m = fmaxf(v0, v1);
#pragma unroll
    for (int o = 16; o; o >>= 1) m = fmaxf(m, __shfl_xor_sync(0xffffffffu, m, o));
    if ((tid & 31) == 0) red[tid >> 5] = m;
    __syncthreads();
    if (tid == 0) {
        float mm = red[0];
        for (int w = 1; w < 8; w++) mm = fmaxf(mm, red[w]);
        red[0] = mm;
    }
    __syncthreads();
    float M = red[0];
    float e0 = __expf(v0 - M), e1 = __expf(v1 - M);
    float s = e0 + e1;
#pragma unroll
    for (int o = 16; o; o >>= 1) s += __shfl_xor_sync(0xffffffffu, s, o);
    if ((tid & 31) == 0) red2[tid >> 5] = s;
    __syncthreads();
    if (tid == 0) {
        float ss = 0.f;
        for (int w = 0; w < 8; w++) ss += red2[w];
        red2[0] = ss;
    }
    __syncthreads();
    float inv = 1.f / red2[0];
    p[tid] = e0 * inv;
    p[tid + 256] = e1 * inv;
}

// ---------------- K6: c_i[b] = a[b] @ LSTM[b] (128x512x512 per b) ------------
__global__ void k_av(const float* __restrict__ LSTM) {
    __shared__ float As[128][17];
    __shared__ float Ls[16][128];
    int tid = threadIdx.x;
    int tx = tid & 15, ty = tid >> 4;
    int b = blockIdx.y;
    int e0 = blockIdx.x * 128;
    const float* Ab = g_E + b * TD * TE;
    const float* Lb = LSTM + b * TE * EHD;
    float acc[8][8];
#pragma unroll
    for (int a = 0; a < 8; a++)
#pragma unroll
        for (int c = 0; c < 8; c++) acc[a][c] = 0.f;

    for (int k0 = 0; k0 < TE; k0 += 16) {
#pragma unroll
        for (int r = 0; r < 8; r++) {
            int lin = tid + 256 * r;
            int row = lin >> 4, kk = lin & 15;
            As[row][kk] = Ab[row * TE + k0 + kk];
        }
#pragma unroll
        for (int r = 0; r < 8; r++) {
            int lin = tid + 256 * r;
            int kk = lin >> 7, e = lin & 127;
            Ls[kk][e] = Lb[(k0 + kk) * EHD + e0 + e];
        }
        __syncthreads();
#pragma unroll
        for (int kk = 0; kk < 16; kk++) {
            float av[8], lv[8];
#pragma unroll
            for (int mi = 0; mi < 8; mi++) av[mi] = As[ty + 16 * mi][kk];
#pragma unroll
            for (int ni = 0; ni < 8; ni++) lv[ni] = Ls[kk][tx + 16 * ni];
#pragma unroll
            for (int mi = 0; mi < 8; mi++)
#pragma unroll
                for (int ni = 0; ni < 8; ni++)
                    acc[mi][ni] += av[mi] * lv[ni];
        }
        __syncthreads();
    }
#pragma unroll
    for (int mi = 0; mi < 8; mi++) {
        int i = ty + 16 * mi;
#pragma unroll
        for (int ni = 0; ni < 8; ni++)
            g_ci[(b * TD + i) * EHD + e0 + tx + 16 * ni] = acc[mi][ni];
    }
}

// ---------------- K7: gates GEMM (x @ Wih.T) fused with LSTM cell ------------
__global__ void k_gates(const float* __restrict__ Wih, const float* __restrict__ m_i,
                        float* __restrict__ out) {
    __shared__ float Xs[64][33];
    __shared__ float Ws[256][33];   // 4 gates x 64 d columns, each row = one Wih row
    int tid = threadIdx.x;
    int tx = tid & 15, ty = tid >> 4;
    int m0 = blockIdx.x * 64;       // flat (b*128+i) tile; b constant per block
    int d0 = blockIdx.y * 64;
    int b = m0 >> 7;
    float acc[4][4][4];
#pragma unroll
    for (int a = 0; a < 4; a++)
#pragma unroll
        for (int c = 0; c < 4; c++)
#pragma unroll
            for (int g = 0; g < 4; g++) acc[a][c][g] = 0.f;

    for (int k0 = 0; k0 < KW; k0 += 32) {
#pragma unroll
        for (int r = 0; r < 8; r++) {
            int lin = tid + 256 * r;
            int row = lin >> 5, kk = lin & 31;
            int k = k0 + kk;
            float v = 0.f;
            if (k < EHD)     v = g_ci[(m0 + row) * EHD + k];
            else if (k < KW) v = g_cp[b * CC + (k - EHD)];
            Xs[row][kk] = v;
        }
#pragma unroll
        for (int r = 0; r < 32; r++) {
            int lin = tid + 256 * r;
            int col = lin >> 5, kk = lin & 31;
            int k = k0 + kk;
            int g = col >> 6, dd = col & 63;
            Ws[col][kk] = (k < KW) ? Wih[(g * DHD + d0 + dd) * KW + k] : 0.f;
        }
        __syncthreads();
#pragma unroll
        for (int kk = 0; kk < 32; kk++) {
            float xv[4], wv[16];
#pragma unroll
            for (int jm = 0; jm < 4; jm++) xv[jm] = Xs[ty + 16 * jm][kk];
#pragma unroll
            for (int jd = 0; jd < 4; jd++)
#pragma unroll
                for (int g = 0; g < 4; g++)
                    wv[jd * 4 + g] = Ws[g * 64 + tx + 16 * jd][kk];
#pragma unroll
            for (int jm = 0; jm < 4; jm++)
#pragma unroll
                for (int jd = 0; jd < 4; jd++)
#pragma unroll
                    for (int g = 0; g < 4; g++)
                        acc[jm][jd][g] += xv[jm] * wv[jd * 4 + g];
        }
        __syncthreads();
    }
#pragma unroll
    for (int jm = 0; jm < 4; jm++) {
        int m = m0 + ty + 16 * jm;
#pragma unroll
        for (int jd = 0; jd < 4; jd++) {
            int d = d0 + tx + 16 * jd;
            const float* shp = g_sh + b * 4 * DHD + d;
            float ig = acc[jm][jd][0] + shp[0];
            float fg = acc[jm][jd][1] + shp[DHD];
            float gg = acc[jm][jd][2] + shp[2 * DHD];
            float og = acc[jm][jd][3] + shp[3 * DHD];
            float cnew = sigm(fg) * m_i[b * DHD + d] + sigm(ig) * tanhf(gg);
            out[m * DHD + d] = sigm(og) * tanhf(cnew);
        }
    }
}

// ---------------- launch -----------------------------------------------------
extern "C" void kernel_launch(void* const* d_in, const int* in_sizes, int n_in,
                              void* d_out, int out_size) {
    const float* LSTM  = (const float*)d_in[0];
    const float* CNNs  = (const float*)d_in[1];
    const float* Wa_w  = (const float*)d_in[2];
    const float* Wa_b  = (const float*)d_in[3];
    const float* Ua_w  = (const float*)d_in[4];
    const float* Ua_b  = (const float*)d_in[5];
    const float* va_w  = (const float*)d_in[6];
    const float* va_b  = (const float*)d_in[7];
    const float* phi_w = (const float*)d_in[8];
    const float* phi_b = (const float*)d_in[9];
    const float* Wih   = (const float*)d_in[10];
    const float* Whh   = (const float*)d_in[11];
    const float* bih   = (const float*)d_in[12];
    const float* bhh   = (const float*)d_in[13];
    const float* wij_w = (const float*)d_in[14];
    const float* wij_b = (const float*)d_in[15];
    const float* s_i   = (const float*)d_in[16];
    const float* m_i   = (const float*)d_in[17];
    float* out = (float*)d_out;

    k_phi<<<EHD, TE>>>(phi_w, phi_b);
    k_prep<<<35, 256>>>(s_i, Wa_w, Wa_b, Whh, bhh, bih, wij_w, wij_b);
    k_cnn<<<1, 896>>>(CNNs, wij_w);
    k_escore<<<dim3(8, 128), 256>>>(LSTM, Ua_w, Ua_b, va_w, va_b);
    k_softmax<<<BB * TD, 256>>>();
    k_av<<<dim3(4, 128), 256>>>(LSTM);
    k_gates<<<dim3(256, 8), 256>>>(Wih, m_i, out);
}

// round 3
// speedup vs baseline: 1.7647x; 1.7647x over previous
#include <cuda_runtime.h>
#include <cstdint>

#define BB 128
#define TE 512
#define TD 128
#define EHD 512
#define DHD 512
#define KC 7
#define CC 105
#define KW 617   // CC + DHD

// ---------------- scratch (device globals; no allocations allowed) -----------
__device__ float g_phi[TE * EHD];          // phi[t][e]
__device__ float g_Wa[BB * TD];            // Wa + Wa_b
__device__ float g_sh[BB * 4 * DHD];       // s_i@Whh.T + bhh + bih
__device__ float g_sdot[BB * KC];          // s_i@w_s.T + wij_b
__device__ float g_cp[BB * CC];            // c_p
__device__ float g_E[BB * TD * TE];        // scores -> softmax in place
__device__ float g_ci[BB * TD * EHD];      // attention output

__device__ __forceinline__ float sigm(float x) { return 1.f / (1.f + __expf(-x)); }
__device__ __forceinline__ uint32_t f2tf(float f) {
    uint32_t u; asm("cvt.rna.tf32.f32 %0, %1;" : "=r"(u) : "f"(f)); return u;
}
__device__ __forceinline__ void mma_tf32(float* d, const uint32_t* a, const uint32_t* b) {
    asm volatile("mma.sync.aligned.m16n8k8.row.col.f32.tf32.tf32.f32 "
                 "{%0,%1,%2,%3}, {%4,%5,%6,%7}, {%8,%9}, {%0,%1,%2,%3};"
                 : "+f"(d[0]), "+f"(d[1]), "+f"(d[2]), "+f"(d[3])
                 : "r"(a[0]), "r"(a[1]), "r"(a[2]), "r"(a[3]), "r"(b[0]), "r"(b[1]));
}

// ---------------- K1: phi[t][e] = phi_b[e] + sum_{t'<t} phi_w[e][t'] ---------
__global__ void k_phi(const float* __restrict__ phi_w, const float* __restrict__ phi_b) {
    int e = blockIdx.x, t = threadIdx.x;
    __shared__ float s[2][TE];
    s[0][t] = phi_w[e * TE + t];
    __syncthreads();
    int src = 0;
    for (int off = 1; off < TE; off <<= 1) {
        float v = s[src][t];
        if (t >= off) v += s[src][t - off];
        s[src ^ 1][t] = v;
        __syncthreads();
        src ^= 1;
    }
    g_phi[t * EHD + e] = phi_b[e] + (t ? s[src][t - 1] : 0.f);
}

// ---------------- K2: fused small GEMM: C = s_i @ W.T for [Wa_w; Whh; w_s] ---
#define N2 2183   // 128 + 2048 + 7
__global__ void k_prep(const float* __restrict__ s_i,
                       const float* __restrict__ Wa_w, const float* __restrict__ Wa_b,
                       const float* __restrict__ Whh,  const float* __restrict__ bhh,
                       const float* __restrict__ bih,
                       const float* __restrict__ wij_w, const float* __restrict__ wij_b) {
    __shared__ float As[128][33];
    __shared__ float Ws[64][33];
    int tid = threadIdx.x;
    int tx = tid & 15, ty = tid >> 4;
    int n0 = blockIdx.x * 64;
    float acc[8][4];
#pragma unroll
    for (int a = 0; a < 8; a++)
#pragma unroll
        for (int c = 0; c < 4; c++) acc[a][c] = 0.f;

    for (int k0 = 0; k0 < DHD; k0 += 32) {
#pragma unroll
        for (int r = 0; r < 16; r++) {
            int lin = tid + 256 * r;
            int row = lin >> 5, kk = lin & 31;
            As[row][kk] = s_i[row * DHD + k0 + kk];
        }
#pragma unroll
        for (int r = 0; r < 8; r++) {
            int lin = tid + 256 * r;
            int col = lin >> 5, kk = lin & 31;
            int n = n0 + col, k = k0 + kk;
            float v = 0.f;
            if (n < TD)                 v = Wa_w[n * DHD + k];
            else if (n < TD + 4 * DHD)  v = Whh[(n - TD) * DHD + k];
            else if (n < N2)            v = wij_w[(n - TD - 4 * DHD) * KW + CC + k];
            Ws[col][kk] = v;
        }
        __syncthreads();
#pragma unroll
        for (int kk = 0; kk < 32; kk++) {
            float xv[8], wv[4];
#pragma unroll
            for (int jm = 0; jm < 8; jm++) xv[jm] = As[ty + 16 * jm][kk];
#pragma unroll
            for (int jn = 0; jn < 4; jn++) wv[jn] = Ws[tx + 16 * jn][kk];
#pragma unroll
            for (int jm = 0; jm < 8; jm++)
#pragma unroll
                for (int jn = 0; jn < 4; jn++) acc[jm][jn] += xv[jm] * wv[jn];
        }
        __syncthreads();
    }
#pragma unroll
    for (int jm = 0; jm < 8; jm++) {
        int m = ty + 16 * jm;
#pragma unroll
        for (int jn = 0; jn < 4; jn++) {
            int n = n0 + tx + 16 * jn;
            float v = acc[jm][jn];
            if (n < TD)                g_Wa[m * TD + n] = v + Wa_b[n];
            else if (n < TD + 4 * DHD) g_sh[m * 4 * DHD + (n - TD)] = v + bhh[n - TD] + bih[n - TD];
            else if (n < N2)           g_sdot[m * KC + (n - TD - 4 * DHD)] = v + wij_b[n - TD - 4 * DHD];
        }
    }
}

// ---------------- K3: CNN path: ep, global-scalar-normalized ap, c_p ---------
__global__ void k_cnn(const float* __restrict__ CNNs, const float* __restrict__ wij_w) {
    __shared__ float ep_s[BB * KC];
    __shared__ float red[32];
    __shared__ float Ssh;
    int tid = threadIdx.x;     // 896 threads, one per (b,k)
    int k = tid % KC;
    float acc = g_sdot[tid];
    const float* crow = CNNs + tid * CC;
    const float* wrow = wij_w + k * KW;
#pragma unroll 5
    for (int c = 0; c < CC; c++) acc += crow[c] * wrow[c];
    float epv = tanhf(acc);

    float v = epv;
#pragma unroll
    for (int o = 16; o; o >>= 1) v += __shfl_xor_sync(0xffffffffu, v, o);
    if ((tid & 31) == 0) red[tid >> 5] = v;
    __syncthreads();
    if (tid == 0) {
        float s = 0.f;
        for (int w = 0; w < 28; w++) s += red[w];
        Ssh = s;            // NOTE: reference divides by sum of ep (not exp(ep))
    }
    __syncthreads();
    ep_s[tid] = __expf(epv) / Ssh;
    __syncthreads();
    for (int o = tid; o < BB * CC; o += 896) {
        int b = o / CC, c = o % CC;
        float s = 0.f;
#pragma unroll
        for (int kk = 0; kk < KC; kk++)
            s += ep_s[b * KC + kk] * CNNs[(b * KC + kk) * CC + c];
        g_cp[o] = s;
    }
}

// ---------------- K4: banded score GEMM + tanh/va assembly -------------------
__global__ void k_escore(const float* __restrict__ LSTM, const float* __restrict__ Ua_w,
                         const float* __restrict__ Ua_b, const float* __restrict__ va_w,
                         const float* __restrict__ va_b) {
    __shared__ float Us[192][33];
    __shared__ float Ps[64][33];
    int tid = threadIdx.x;
    int tx = tid & 15, ty = tid >> 4;
    int t0 = blockIdx.x * 64;
    int b = blockIdx.y;
    int s_lo = 321 - t0;
    const float* Lb = LSTM + b * TE * EHD;
    float acc[4][8];
#pragma unroll
    for (int a = 0; a < 4; a++)
#pragma unroll
        for (int c = 0; c < 8; c++) acc[a][c] = 0.f;

    for (int k0 = 0; k0 < EHD; k0 += 32) {
#pragma unroll
        for (int r = 0; r < 24; r++) {
            int lin = tid + 256 * r;
            int row = lin >> 5, kk = lin & 31;
            int s = s_lo + row;
            Us[row][kk] = ((unsigned)s < 512u) ? Ua_w[s * EHD + k0 + kk] : 0.f;
        }
#pragma unroll
        for (int r = 0; r < 8; r++) {
            int lin = tid + 256 * r;
            int row = lin >> 5, kk = lin & 31;
            int t = t0 + row;
            Ps[row][kk] = g_phi[t * EHD + k0 + kk] * Lb[t * EHD + k0 + kk];
        }
        __syncthreads();
        int base2 = 15 + ty - tx;
#pragma unroll
        for (int kk = 0; kk < 32; kk++) {
            float p[4], u[11];
#pragma unroll
            for (int tt = 0; tt < 4; tt++) p[tt] = Ps[tx + 16 * tt][kk];
#pragma unroll
            for (int di = 0; di < 11; di++) u[di] = Us[base2 + 16 * di][kk];
#pragma unroll
            for (int tt = 0; tt < 4; tt++)
#pragma unroll
                for (int ii = 0; ii < 8; ii++)
                    acc[tt][ii] += p[tt] * u[ii - tt + 3];
        }
        __syncthreads();
    }
    float vb = va_b[0];
#pragma unroll
    for (int tt = 0; tt < 4; tt++) {
        int t = t0 + tx + 16 * tt;
#pragma unroll
        for (int ii = 0; ii < 8; ii++) {
            int i = ty + 16 * ii;
            int s = i + 384 - t;
            int jc = s + 128;
            float ev;
            if (s >= 0) ev = tanhf(acc[tt][ii] + Ua_b[s]) * va_w[jc] + vb;
            else        ev = tanhf(g_Wa[b * TD + jc]) * va_w[jc] + vb;
            g_E[(b * TD + i) * TE + t] = ev;
        }
    }
}

// ---------------- K5: row softmax over t (in place on g_E) -------------------
__global__ void k_softmax() {
    int row = blockIdx.x;
    float* p = g_E + row * TE;
    int tid = threadIdx.x;   // 256
    __shared__ float red[8], red2[8];
    float v0 = p[tid], v1 = p[tid + 256];
    float m = fmaxf(v0, v1);
#pragma unroll
    for (int o = 16; o; o >>= 1) m = fmaxf(m, __shfl_xor_sync(0xffffffffu, m, o));
    if ((tid & 31) == 0) red[tid >> 5] = m;
    __syncthreads();
    if (tid == 0) {
        float mm = red[0];
        for (int w = 1; w < 8; w++) mm = fmaxf(mm, red[w]);
        red[0] = mm;
    }
    __syncthreads();
    float M = red[0];
    float e0 = __expf(v0 - M), e1 = __expf(v1 - M);
    float s = e0 + e1;
#pragma unroll
    for (int o = 16; o; o >>= 1) s += __shfl_xor_sync(0xffffffffu, s, o);
    if ((tid & 31) == 0) red2[tid >> 5] = s;
    __syncthreads();
    if (tid == 0) {
        float ss = 0.f;
        for (int w = 0; w < 8; w++) ss += red2[w];
        red2[0] = ss;
    }
    __syncthreads();
    float inv = 1.f / red2[0];
    p[tid] = e0 * inv;
    p[tid + 256] = e1 * inv;
}

// ---------------- K6: c_i[b] = a[b] @ LSTM[b] (128x512x512 per b) ------------
__global__ void k_av(const float* __restrict__ LSTM) {
    __shared__ float As[128][17];
    __shared__ float Ls[16][128];
    int tid = threadIdx.x;
    int tx = tid & 15, ty = tid >> 4;
    int b = blockIdx.y;
    int e0 = blockIdx.x * 128;
    const float* Ab = g_E + b * TD * TE;
    const float* Lb = LSTM + b * TE * EHD;
    float acc[8][8];
#pragma unroll
    for (int a = 0; a < 8; a++)
#pragma unroll
        for (int c = 0; c < 8; c++) acc[a][c] = 0.f;

    for (int k0 = 0; k0 < TE; k0 += 16) {
#pragma unroll
        for (int r = 0; r < 8; r++) {
            int lin = tid + 256 * r;
            int row = lin >> 4, kk = lin & 15;
            As[row][kk] = Ab[row * TE + k0 + kk];
        }
#pragma unroll
        for (int r = 0; r < 8; r++) {
            int lin = tid + 256 * r;
            int kk = lin >> 7, e = lin & 127;
            Ls[kk][e] = Lb[(k0 + kk) * EHD + e0 + e];
        }
        __syncthreads();
#pragma unroll
        for (int kk = 0; kk < 16; kk++) {
            float av[8], lv[8];
#pragma unroll
            for (int mi = 0; mi < 8; mi++) av[mi] = As[ty + 16 * mi][kk];
#pragma unroll
            for (int ni = 0; ni < 8; ni++) lv[ni] = Ls[kk][tx + 16 * ni];
#pragma unroll
            for (int mi = 0; mi < 8; mi++)
#pragma unroll
                for (int ni = 0; ni < 8; ni++)
                    acc[mi][ni] += av[mi] * lv[ni];
        }
        __syncthreads();
    }
#pragma unroll
    for (int mi = 0; mi < 8; mi++) {
        int i = ty + 16 * mi;
#pragma unroll
        for (int ni = 0; ni < 8; ni++)
            g_ci[(b * TD + i) * EHD + e0 + tx + 16 * ni] = acc[mi][ni];
    }
}

// ======== K7: gates GEMM via mma.sync tf32 (HMMA) + fused LSTM cell =========
// CTA tile: M=128 (one batch b), N=128 = 4 gates x 32 d.  col c -> n = (c>>5)*512 + d0 + (c&31)
// K padded 617 -> 640, chunks of 32, double-buffered smem (stride 36 = conflict-free quads).
#define NTK 20
#define SA 36
#define SSTG 132
#define SMEMG 73728   // bytes: 4 buffers of 128*36 floats

__device__ __forceinline__ void g_ldA(float4* aR, int kt, int m0, int b, int tid) {
#pragma unroll
    for (int r = 0; r < 4; r++) {
        int lin = tid + 256 * r;
        int row = lin >> 3, q = lin & 7;
        int k = kt * 32 + 4 * q;
        float4 v;
        if (kt < 16) {
            v = *(const float4*)(g_ci + (size_t)(m0 + row) * EHD + k);
        } else {
            v.x = (k + 0 < KW) ? g_cp[b * CC + k - EHD + 0] : 0.f;
            v.y = (k + 1 < KW) ? g_cp[b * CC + k - EHD + 1] : 0.f;
            v.z = (k + 2 < KW) ? g_cp[b * CC + k - EHD + 2] : 0.f;
            v.w = (k + 3 < KW) ? g_cp[b * CC + k - EHD + 3] : 0.f;
        }
        aR[r] = v;
    }
}
__device__ __forceinline__ void g_ldB(float* bR, int kt, int d0,
                                      const float* __restrict__ Wih, int tid) {
#pragma unroll
    for (int r = 0; r < 16; r++) {
        int lin = tid + 256 * r;
        int kk = lin & 31, c = lin >> 5;
        int n = ((c >> 5) << 9) + d0 + (c & 31);
        int k = kt * 32 + kk;
        bR[r] = (k < KW) ? Wih[(size_t)n * KW + k] : 0.f;
    }
}
__device__ __forceinline__ void g_stA(float* smA, const float4* aR, int tid) {
#pragma unroll
    for (int r = 0; r < 4; r++) {
        int lin = tid + 256 * r;
        int row = lin >> 3, q = lin & 7;
        uint4 o;
        o.x = f2tf(aR[r].x); o.y = f2tf(aR[r].y); o.z = f2tf(aR[r].z); o.w = f2tf(aR[r].w);
        *(uint4*)(smA + row * SA + 4 * q) = o;
    }
}
__device__ __forceinline__ void g_stB(float* smB, const float* bR, int tid) {
#pragma unroll
    for (int r = 0; r < 16; r++) {
        int lin = tid + 256 * r;
        int kk = lin & 31, c = lin >> 5;
        smB[c * SA + kk] = __uint_as_float(f2tf(bR[r]));
    }
}
__device__ __forceinline__ void g_compute(const float* smA, const float* smB,
                                          float acc[2][8][4], int lane, int wm, int wn) {
    int g = lane >> 2, t = lane & 3;
#pragma unroll
    for (int ks = 0; ks < 4; ks++) {
        uint32_t af[2][4];
#pragma unroll
        for (int mt = 0; mt < 2; mt++) {
            const float* p = smA + (wm * 32 + mt * 16 + g) * SA + ks * 8 + t;
            af[mt][0] = __float_as_uint(p[0]);
            af[mt][1] = __float_as_uint(p[8 * SA]);
            af[mt][2] = __float_as_uint(p[4]);
            af[mt][3] = __float_as_uint(p[8 * SA + 4]);
        }
#pragma unroll
        for (int nt = 0; nt < 8; nt++) {
            const float* q = smB + (wn * 64 + nt * 8 + g) * SA + ks * 8 + t;
            uint32_t bf[2];
            bf[0] = __float_as_uint(q[0]);
            bf[1] = __float_as_uint(q[4]);
#pragma unroll
            for (int mt = 0; mt < 2; mt++)
                mma_tf32(acc[mt][nt], af[mt], bf);
        }
    }
}

__global__ void __launch_bounds__(256) k_gates_mma(const float* __restrict__ Wih,
                                                   const float* __restrict__ m_i,
                                                   float* __restrict__ out) {
    extern __shared__ float sm[];
    int tid = threadIdx.x, lane = tid & 31, wid = tid >> 5;
    int wm = wid >> 1, wn = wid & 1;
    int b = blockIdx.x, m0 = b * 128, d0 = blockIdx.y * 32;

    float acc[2][8][4];
#pragma unroll
    for (int i = 0; i < 2; i++)
#pragma unroll
        for (int j = 0; j < 8; j++)
#pragma unroll
            for (int k = 0; k < 4; k++) acc[i][j][k] = 0.f;

    float* Abuf[2] = {sm, sm + 4608};
    float* Bbuf[2] = {sm + 9216, sm + 13824};

    float4 aR[4];
    float bR[16];
    g_ldA(aR, 0, m0, b, tid);
    g_ldB(bR, 0, d0, Wih, tid);
    g_stA(Abuf[0], aR, tid);
    g_stB(Bbuf[0], bR, tid);
    __syncthreads();

#pragma unroll 1
    for (int kt = 0; kt < NTK; kt++) {
        int cur = kt & 1;
        if (kt + 1 < NTK) {
            g_ldA(aR, kt + 1, m0, b, tid);
            g_ldB(bR, kt + 1, d0, Wih, tid);
        }
        g_compute(Abuf[cur], Bbuf[cur], acc, lane, wm, wn);
        if (kt + 1 < NTK) {
            g_stA(Abuf[cur ^ 1], aR, tid);
            g_stB(Bbuf[cur ^ 1], bR, tid);
        }
        __syncthreads();
    }

    // -------- epilogue: stage accum tile to smem, then fused LSTM cell --------
    float* stg = sm;    // reuse (all compute reads done after final sync)
    int g = lane >> 2, t = lane & 3;
#pragma unroll
    for (int mt = 0; mt < 2; mt++) {
        int r0 = wm * 32 + mt * 16 + g;
#pragma unroll
        for (int nt = 0; nt < 8; nt++) {
            int c0 = wn * 64 + nt * 8 + 2 * t;
            stg[r0 * SSTG + c0]           = acc[mt][nt][0];
            stg[r0 * SSTG + c0 + 1]       = acc[mt][nt][1];
            stg[(r0 + 8) * SSTG + c0]     = acc[mt][nt][2];
            stg[(r0 + 8) * SSTG + c0 + 1] = acc[mt][nt][3];
        }
    }
    __syncthreads();
    int r = tid >> 1, h = tid & 1;
    const float* shp = g_sh + b * 4 * DHD;
    const float* mip = m_i + b * DHD;
#pragma unroll
    for (int j = 0; j < 16; j++) {
        int dd = h * 16 + j;
        int d = d0 + dd;
        float ig = stg[r * SSTG + dd]      + shp[d];
        float fg = stg[r * SSTG + 32 + dd] + shp[DHD + d];
        float gg = stg[r * SSTG + 64 + dd] + shp[2 * DHD + d];
        float og = stg[r * SSTG + 96 + dd] + shp[3 * DHD + d];
        float cnew = sigm(fg) * mip[d] + sigm(ig) * tanhf(gg);
        out[(size_t)(m0 + r) * DHD + d] = sigm(og) * tanhf(cnew);
    }
}

// ---------------- launch -----------------------------------------------------
extern "C" void kernel_launch(void* const* d_in, const int* in_sizes, int n_in,
                              void* d_out, int out_size) {
    const float* LSTM  = (const float*)d_in[0];
    const float* CNNs  = (const float*)d_in[1];
    const float* Wa_w  = (const float*)d_in[2];
    const float* Wa_b  = (const float*)d_in[3];
    const float* Ua_w  = (const float*)d_in[4];
    const float* Ua_b  = (const float*)d_in[5];
    const float* va_w  = (const float*)d_in[6];
    const float* va_b  = (const float*)d_in[7];
    const float* phi_w = (const float*)d_in[8];
    const float* phi_b = (const float*)d_in[9];
    const float* Wih   = (const float*)d_in[10];
    const float* Whh   = (const float*)d_in[11];
    const float* bih   = (const float*)d_in[12];
    const float* bhh   = (const float*)d_in[13];
    const float* wij_w = (const float*)d_in[14];
    const float* wij_b = (const float*)d_in[15];
    const float* s_i   = (const float*)d_in[16];
    const float* m_i   = (const float*)d_in[17];
    float* out = (float*)d_out;

    static int smem_set = 0;
    if (!smem_set) {
        cudaFuncSetAttribute(k_gates_mma, cudaFuncAttributeMaxDynamicSharedMemorySize, SMEMG);
        smem_set = 1;
    }

    k_phi<<<EHD, TE>>>(phi_w, phi_b);
    k_prep<<<35, 256>>>(s_i, Wa_w, Wa_b, Whh, bhh, bih, wij_w, wij_b);
    k_cnn<<<1, 896>>>(CNNs, wij_w);
    k_escore<<<dim3(8, 128), 256>>>(LSTM, Ua_w, Ua_b, va_w, va_b);
    k_softmax<<<BB * TD, 256>>>();
    k_av<<<dim3(4, 128), 256>>>(LSTM);
    k_gates_mma<<<dim3(128, 16), 256, SMEMG>>>(Wih, m_i, out);
}

// round 4
// speedup vs baseline: 2.4118x; 1.3667x over previous
#include <cuda_runtime.h>
#include <cstdint>

#define BB 128
#define TE 512
#define TD 128
#define EHD 512
#define DHD 512
#define KC 7
#define CC 105
#define KW 617   // CC + DHD

// ---------------- scratch (device globals; no allocations allowed) -----------
__device__ float g_phi[TE * EHD];          // phi[t][e]
__device__ float g_Wa[BB * TD];            // Wa + Wa_b
__device__ float g_sh[BB * 4 * DHD];       // s_i@Whh.T + bhh + bih
__device__ float g_sdot[BB * KC];          // s_i@w_s.T + wij_b
__device__ float g_cp[BB * CC];            // c_p
__device__ float g_E[BB * TD * TE];        // scores -> softmax in place
__device__ float g_ci[BB * TD * EHD];      // attention output

__device__ __forceinline__ float sigm(float x) { return 1.f / (1.f + __expf(-x)); }
__device__ __forceinline__ uint32_t f2tf(float f) {
    uint32_t u; asm("cvt.rna.tf32.f32 %0, %1;" : "=r"(u) : "f"(f)); return u;
}
__device__ __forceinline__ void mma_tf32(float* d, const uint32_t* a, const uint32_t* b) {
    asm volatile("mma.sync.aligned.m16n8k8.row.col.f32.tf32.tf32.f32 "
                 "{%0,%1,%2,%3}, {%4,%5,%6,%7}, {%8,%9}, {%0,%1,%2,%3};"
                 : "+f"(d[0]), "+f"(d[1]), "+f"(d[2]), "+f"(d[3])
                 : "r"(a[0]), "r"(a[1]), "r"(a[2]), "r"(a[3]), "r"(b[0]), "r"(b[1]));
}

// ---------------- K1: phi[t][e] = phi_b[e] + sum_{t'<t} phi_w[e][t'] ---------
__global__ void k_phi(const float* __restrict__ phi_w, const float* __restrict__ phi_b) {
    int e = blockIdx.x, t = threadIdx.x;
    __shared__ float s[2][TE];
    s[0][t] = phi_w[e * TE + t];
    __syncthreads();
    int src = 0;
    for (int off = 1; off < TE; off <<= 1) {
        float v = s[src][t];
        if (t >= off) v += s[src][t - off];
        s[src ^ 1][t] = v;
        __syncthreads();
        src ^= 1;
    }
    g_phi[t * EHD + e] = phi_b[e] + (t ? s[src][t - 1] : 0.f);
}

// ---------------- K2: fused small GEMM: C = s_i @ W.T for [Wa_w; Whh; w_s] ---
#define N2 2183   // 128 + 2048 + 7
__global__ void k_prep(const float* __restrict__ s_i,
                       const float* __restrict__ Wa_w, const float* __restrict__ Wa_b,
                       const float* __restrict__ Whh,  const float* __restrict__ bhh,
                       const float* __restrict__ bih,
                       const float* __restrict__ wij_w, const float* __restrict__ wij_b) {
    __shared__ float As[128][33];
    __shared__ float Ws[64][33];
    int tid = threadIdx.x;
    int tx = tid & 15, ty = tid >> 4;
    int n0 = blockIdx.x * 64;
    float acc[8][4];
#pragma unroll
    for (int a = 0; a < 8; a++)
#pragma unroll
        for (int c = 0; c < 4; c++) acc[a][c] = 0.f;

    for (int k0 = 0; k0 < DHD; k0 += 32) {
#pragma unroll
        for (int r = 0; r < 16; r++) {
            int lin = tid + 256 * r;
            int row = lin >> 5, kk = lin & 31;
            As[row][kk] = s_i[row * DHD + k0 + kk];
        }
#pragma unroll
        for (int r = 0; r < 8; r++) {
            int lin = tid + 256 * r;
            int col = lin >> 5, kk = lin & 31;
            int n = n0 + col, k = k0 + kk;
            float v = 0.f;
            if (n < TD)                 v = Wa_w[n * DHD + k];
            else if (n < TD + 4 * DHD)  v = Whh[(n - TD) * DHD + k];
            else if (n < N2)            v = wij_w[(n - TD - 4 * DHD) * KW + CC + k];
            Ws[col][kk] = v;
        }
        __syncthreads();
#pragma unroll
        for (int kk = 0; kk < 32; kk++) {
            float xv[8], wv[4];
#pragma unroll
            for (int jm = 0; jm < 8; jm++) xv[jm] = As[ty + 16 * jm][kk];
#pragma unroll
            for (int jn = 0; jn < 4; jn++) wv[jn] = Ws[tx + 16 * jn][kk];
#pragma unroll
            for (int jm = 0; jm < 8; jm++)
#pragma unroll
                for (int jn = 0; jn < 4; jn++) acc[jm][jn] += xv[jm] * wv[jn];
        }
        __syncthreads();
    }
#pragma unroll
    for (int jm = 0; jm < 8; jm++) {
        int m = ty + 16 * jm;
#pragma unroll
        for (int jn = 0; jn < 4; jn++) {
            int n = n0 + tx + 16 * jn;
            float v = acc[jm][jn];
            if (n < TD)                g_Wa[m * TD + n] = v + Wa_b[n];
            else if (n < TD + 4 * DHD) g_sh[m * 4 * DHD + (n - TD)] = v + bhh[n - TD] + bih[n - TD];
            else if (n < N2)           g_sdot[m * KC + (n - TD - 4 * DHD)] = v + wij_b[n - TD - 4 * DHD];
        }
    }
}

// ---------------- K3: CNN path: ep, global-scalar-normalized ap, c_p ---------
__global__ void k_cnn(const float* __restrict__ CNNs, const float* __restrict__ wij_w) {
    __shared__ float ep_s[BB * KC];
    __shared__ float red[32];
    __shared__ float Ssh;
    int tid = threadIdx.x;     // 896 threads, one per (b,k)
    int k = tid % KC;
    float acc = g_sdot[tid];
    const float* crow = CNNs + tid * CC;
    const float* wrow = wij_w + k * KW;
#pragma unroll 5
    for (int c = 0; c < CC; c++) acc += crow[c] * wrow[c];
    float epv = tanhf(acc);

    float v = epv;
#pragma unroll
    for (int o = 16; o; o >>= 1) v += __shfl_xor_sync(0xffffffffu, v, o);
    if ((tid & 31) == 0) red[tid >> 5] = v;
    __syncthreads();
    if (tid == 0) {
        float s = 0.f;
        for (int w = 0; w < 28; w++) s += red[w];
        Ssh = s;            // NOTE: reference divides by sum of ep (not exp(ep))
    }
    __syncthreads();
    ep_s[tid] = __expf(epv) / Ssh;
    __syncthreads();
    for (int o = tid; o < BB * CC; o += 896) {
        int b = o / CC, c = o % CC;
        float s = 0.f;
#pragma unroll
        for (int kk = 0; kk < KC; kk++)
            s += ep_s[b * KC + kk] * CNNs[(b * KC + kk) * CC + c];
        g_cp[o] = s;
    }
}

// ========== K4: banded score GEMM via mma.sync tf32 + tanh/va epilogue =======
// Per CTA: b, 64 t's.  C[tt][s'] = sum_k P[t0+tt][k] * Ua_w[s_lo+s'][k], s' in 0..191.
// e[i][t] uses s' = i - tt + 63.  M=64, N=192, K=512.
__global__ void __launch_bounds__(256) k_escore_mma(const float* __restrict__ LSTM,
                                                    const float* __restrict__ Ua_w,
                                                    const float* __restrict__ Ua_b,
                                                    const float* __restrict__ va_w,
                                                    const float* __restrict__ va_b) {
    extern __shared__ float sm[];
    int tid = threadIdx.x, lane = tid & 31, wid = tid >> 5;
    int g = lane >> 2, t = lane & 3;
    int wm = wid & 1, wn = wid >> 1;           // 2 x 4 warp grid
    int t0 = blockIdx.x * 64, b = blockIdx.y;
    int s_lo = 321 - t0;
    const float* Lb = LSTM + (size_t)b * TE * EHD;
    float* Ab[2] = {sm, sm + 2304};            // 64 x 36
    float* Bb[2] = {sm + 4608, sm + 11520};    // 192 x 36

    float acc[2][6][4];
#pragma unroll
    for (int i = 0; i < 2; i++)
#pragma unroll
        for (int j = 0; j < 6; j++)
#pragma unroll
            for (int k = 0; k < 4; k++) acc[i][j][k] = 0.f;

    float4 aR[2], bR[6];
    auto ldA = [&](int kt) {
#pragma unroll
        for (int r = 0; r < 2; r++) {
            int lin = tid + 256 * r;
            int row = lin >> 3, q = lin & 7;
            int off = (t0 + row) * EHD + kt * 32 + 4 * q;
            float4 p = *(const float4*)(g_phi + off);
            float4 l = *(const float4*)(Lb + off);
            aR[r].x = p.x * l.x; aR[r].y = p.y * l.y;
            aR[r].z = p.z * l.z; aR[r].w = p.w * l.w;
        }
    };
    auto stA = [&](float* A) {
#pragma unroll
        for (int r = 0; r < 2; r++) {
            int lin = tid + 256 * r;
            int row = lin >> 3, q = lin & 7;
            uint4 o = {f2tf(aR[r].x), f2tf(aR[r].y), f2tf(aR[r].z), f2tf(aR[r].w)};
            *(uint4*)(A + row * 36 + 4 * q) = o;
        }
    };
    auto ldB = [&](int kt) {
#pragma unroll
        for (int r = 0; r < 6; r++) {
            int lin = tid + 256 * r;
            int c = lin >> 3, q = lin & 7;
            int s = s_lo + c;
            if ((unsigned)s < 512u)
                bR[r] = *(const float4*)(Ua_w + (size_t)s * EHD + kt * 32 + 4 * q);
            else
                bR[r] = make_float4(0.f, 0.f, 0.f, 0.f);
        }
    };
    auto stB = [&](float* B) {
#pragma unroll
        for (int r = 0; r < 6; r++) {
            int lin = tid + 256 * r;
            int c = lin >> 3, q = lin & 7;
            uint4 o = {f2tf(bR[r].x), f2tf(bR[r].y), f2tf(bR[r].z), f2tf(bR[r].w)};
            *(uint4*)(B + c * 36 + 4 * q) = o;
        }
    };
    auto comp = [&](const float* A, const float* B) {
#pragma unroll
        for (int ks = 0; ks < 4; ks++) {
            uint32_t af[2][4];
#pragma unroll
            for (int mt = 0; mt < 2; mt++) {
                const float* p = A + (wm * 32 + mt * 16 + g) * 36 + ks * 8 + t;
                af[mt][0] = __float_as_uint(p[0]);
                af[mt][1] = __float_as_uint(p[8 * 36]);
                af[mt][2] = __float_as_uint(p[4]);
                af[mt][3] = __float_as_uint(p[8 * 36 + 4]);
            }
#pragma unroll
            for (int nt = 0; nt < 6; nt++) {
                const float* q2 = B + (wn * 48 + nt * 8 + g) * 36 + ks * 8 + t;
                uint32_t bf[2] = {__float_as_uint(q2[0]), __float_as_uint(q2[4])};
                mma_tf32(acc[0][nt], af[0], bf);
                mma_tf32(acc[1][nt], af[1], bf);
            }
        }
    };

    ldA(0); ldB(0);
    stA(Ab[0]); stB(Bb[0]);
    __syncthreads();
#pragma unroll 1
    for (int kt = 0; kt < 16; kt++) {
        int cur = kt & 1;
        if (kt + 1 < 16) { ldA(kt + 1); ldB(kt + 1); }
        comp(Ab[cur], Bb[cur]);
        if (kt + 1 < 16) { stA(Ab[cur ^ 1]); stB(Bb[cur ^ 1]); }
        __syncthreads();
    }

    // stage C [64][192] to smem (stride 196), then band epilogue
    float* stg = sm;
#pragma unroll
    for (int mt = 0; mt < 2; mt++) {
        int r0 = wm * 32 + mt * 16 + g;
#pragma unroll
        for (int nt = 0; nt < 6; nt++) {
            int c0 = wn * 48 + nt * 8 + 2 * t;
            stg[r0 * 196 + c0]           = acc[mt][nt][0];
            stg[r0 * 196 + c0 + 1]       = acc[mt][nt][1];
            stg[(r0 + 8) * 196 + c0]     = acc[mt][nt][2];
            stg[(r0 + 8) * 196 + c0 + 1] = acc[mt][nt][3];
        }
    }
    __syncthreads();
    float vb = va_b[0];
#pragma unroll 1
    for (int r = 0; r < 32; r++) {
        int lin = tid + 256 * r;
        int tt = lin & 63, ii = lin >> 6;
        int sp = ii - tt + 63;
        int s = s_lo + sp;
        int jc = s + 128;
        float ev;
        if (s >= 0) ev = tanhf(stg[tt * 196 + sp] + Ua_b[s]) * va_w[jc] + vb;
        else        ev = tanhf(g_Wa[b * TD + jc]) * va_w[jc] + vb;
        g_E[((size_t)(b * TD + ii)) * TE + t0 + tt] = ev;
    }
}

// ---------------- K5: row softmax over t (in place on g_E) -------------------
__global__ void k_softmax() {
    int row = blockIdx.x;
    float* p = g_E + row * TE;
    int tid = threadIdx.x;   // 256
    __shared__ float red[8], red2[8];
    float v0 = p[tid], v1 = p[tid + 256];
    float m = fmaxf(v0, v1);
#pragma unroll
    for (int o = 16; o; o >>= 1) m = fmaxf(m, __shfl_xor_sync(0xffffffffu, m, o));
    if ((tid & 31) == 0) red[tid >> 5] = m;
    __syncthreads();
    if (tid == 0) {
        float mm = red[0];
        for (int w = 1; w < 8; w++) mm = fmaxf(mm, red[w]);
        red[0] = mm;
    }
    __syncthreads();
    float M = red[0];
    float e0 = __expf(v0 - M), e1 = __expf(v1 - M);
    float s = e0 + e1;
#pragma unroll
    for (int o = 16; o; o >>= 1) s += __shfl_xor_sync(0xffffffffu, s, o);
    if ((tid & 31) == 0) red2[tid >> 5] = s;
    __syncthreads();
    if (tid == 0) {
        float ss = 0.f;
        for (int w = 0; w < 8; w++) ss += red2[w];
        red2[0] = ss;
    }
    __syncthreads();
    float inv = 1.f / red2[0];
    p[tid] = e0 * inv;
    p[tid + 256] = e1 * inv;
}

// ========== K6: c_i[b] = a[b] @ LSTM[b] via mma.sync tf32 ====================
// Per CTA: b, 128 e's.  M=128(i), N=128(e), K=512(t).  B staged k-major, stride 136.
__global__ void __launch_bounds__(256) k_av_mma(const float* __restrict__ LSTM) {
    extern __shared__ float sm[];
    int tid = threadIdx.x, lane = tid & 31, wid = tid >> 5;
    int g = lane >> 2, t = lane & 3;
    int wm = wid >> 1, wn = wid & 1;   // 4 x 2 warp grid
    int e0 = blockIdx.x * 128, b = blockIdx.y;
    const float* Lb = LSTM + (size_t)b * TE * EHD;
    const float* Ag = g_E + (size_t)b * TD * TE;
    float* Ab[2] = {sm, sm + 4608};            // 128 x 36
    float* Bb[2] = {sm + 9216, sm + 13568};    // 32 x 136 (k-major)

    float acc[2][8][4];
#pragma unroll
    for (int i = 0; i < 2; i++)
#pragma unroll
        for (int j = 0; j < 8; j++)
#pragma unroll
            for (int k = 0; k < 4; k++) acc[i][j][k] = 0.f;

    float4 aR[4], bR[4];
    auto ldA = [&](int kt) {
#pragma unroll
        for (int r = 0; r < 4; r++) {
            int lin = tid + 256 * r;
            int row = lin >> 3, q = lin & 7;
            aR[r] = *(const float4*)(Ag + (size_t)row * TE + kt * 32 + 4 * q);
        }
    };
    auto stA = [&](float* A) {
#pragma unroll
        for (int r = 0; r < 4; r++) {
            int lin = tid + 256 * r;
            int row = lin >> 3, q = lin & 7;
            uint4 o = {f2tf(aR[r].x), f2tf(aR[r].y), f2tf(aR[r].z), f2tf(aR[r].w)};
            *(uint4*)(A + row * 36 + 4 * q) = o;
        }
    };
    auto ldB = [&](int kt) {
#pragma unroll
        for (int r = 0; r < 4; r++) {
            int lin = tid + 256 * r;
            int kk = lin >> 5, cq = lin & 31;
            bR[r] = *(const float4*)(Lb + (size_t)(kt * 32 + kk) * EHD + e0 + 4 * cq);
        }
    };
    auto stB = [&](float* B) {
#pragma unroll
        for (int r = 0; r < 4; r++) {
            int lin = tid + 256 * r;
            int kk = lin >> 5, cq = lin & 31;
            uint4 o = {f2tf(bR[r].x), f2tf(bR[r].y), f2tf(bR[r].z), f2tf(bR[r].w)};
            *(uint4*)(B + kk * 136 + 4 * cq) = o;
        }
    };
    auto comp = [&](const float* A, const float* B) {
#pragma unroll
        for (int ks = 0; ks < 4; ks++) {
            uint32_t af[2][4];
#pragma unroll
            for (int mt = 0; mt < 2; mt++) {
                const float* p = A + (wm * 32 + mt * 16 + g) * 36 + ks * 8 + t;
                af[mt][0] = __float_as_uint(p[0]);
                af[mt][1] = __float_as_uint(p[8 * 36]);
                af[mt][2] = __float_as_uint(p[4]);
                af[mt][3] = __float_as_uint(p[8 * 36 + 4]);
            }
            int kb = ks * 8 + t;
#pragma unroll
            for (int nt = 0; nt < 8; nt++) {
                int c0 = wn * 64 + nt * 8 + g;
                uint32_t bf[2] = {__float_as_uint(B[kb * 136 + c0]),
                                  __float_as_uint(B[(kb + 4) * 136 + c0])};
                mma_tf32(acc[0][nt], af[0], bf);
                mma_tf32(acc[1][nt], af[1], bf);
            }
        }
    };

    ldA(0); ldB(0);
    stA(Ab[0]); stB(Bb[0]);
    __syncthreads();
#pragma unroll 1
    for (int kt = 0; kt < 16; kt++) {
        int cur = kt & 1;
        if (kt + 1 < 16) { ldA(kt + 1); ldB(kt + 1); }
        comp(Ab[cur], Bb[cur]);
        if (kt + 1 < 16) { stA(Ab[cur ^ 1]); stB(Bb[cur ^ 1]); }
        __syncthreads();
    }

    // direct epilogue: each 4-lane quad writes full 32B sectors of g_ci
#pragma unroll
    for (int mt = 0; mt < 2; mt++) {
        int r0 = wm * 32 + mt * 16 + g;
#pragma unroll
        for (int nt = 0; nt < 8; nt++) {
            int c = e0 + wn * 64 + nt * 8 + 2 * t;
            *(float2*)(g_ci + (size_t)(b * TD + r0) * EHD + c) =
                make_float2(acc[mt][nt][0], acc[mt][nt][1]);
            *(float2*)(g_ci + (size_t)(b * TD + r0 + 8) * EHD + c) =
                make_float2(acc[mt][nt][2], acc[mt][nt][3]);
        }
    }
}

// ======== K7: gates GEMM via mma.sync tf32 (HMMA) + fused LSTM cell =========
#define NTK 20
#define SA 36
#define SSTG 132
#define SMEMG 73728

__device__ __forceinline__ void g_ldA(float4* aR, int kt, int m0, int b, int tid) {
#pragma unroll
    for (int r = 0; r < 4; r++) {
        int lin = tid + 256 * r;
        int row = lin >> 3, q = lin & 7;
        int k = kt * 32 + 4 * q;
        float4 v;
        if (kt < 16) {
            v = *(const float4*)(g_ci + (size_t)(m0 + row) * EHD + k);
        } else {
            v.x = (k + 0 < KW) ? g_cp[b * CC + k - EHD + 0] : 0.f;
            v.y = (k + 1 < KW) ? g_cp[b * CC + k - EHD + 1] : 0.f;
            v.z = (k + 2 < KW) ? g_cp[b * CC + k - EHD + 2] : 0.f;
            v.w = (k + 3 < KW) ? g_cp[b * CC + k - EHD + 3] : 0.f;
        }
        aR[r] = v;
    }
}
__device__ __forceinline__ void g_ldB(float* bR, int kt, int d0,
                                      const float* __restrict__ Wih, int tid) {
#pragma unroll
    for (int r = 0; r < 16; r++) {
        int lin = tid + 256 * r;
        int kk = lin & 31, c = lin >> 5;
        int n = ((c >> 5) << 9) + d0 + (c & 31);
        int k = kt * 32 + kk;
        bR[r] = (k < KW) ? Wih[(size_t)n * KW + k] : 0.f;
    }
}
__device__ __forceinline__ void g_stA(float* smA, const float4* aR, int tid) {
#pragma unroll
    for (int r = 0; r < 4; r++) {
        int lin = tid + 256 * r;
        int row = lin >> 3, q = lin & 7;
        uint4 o;
        o.x = f2tf(aR[r].x); o.y = f2tf(aR[r].y); o.z = f2tf(aR[r].z); o.w = f2tf(aR[r].w);
        *(uint4*)(smA + row * SA + 4 * q) = o;
    }
}
__device__ __forceinline__ void g_stB(float* smB, const float* bR, int tid) {
#pragma unroll
    for (int r = 0; r < 16; r++) {
        int lin = tid + 256 * r;
        int kk = lin & 31, c = lin >> 5;
        smB[c * SA + kk] = __uint_as_float(f2tf(bR[r]));
    }
}
__device__ __forceinline__ void g_compute(const float* smA, const float* smB,
                                          float acc[2][8][4], int lane, int wm, int wn) {
    int g = lane >> 2, t = lane & 3;
#pragma unroll
    for (int ks = 0; ks < 4; ks++) {
        uint32_t af[2][4];
#pragma unroll
        for (int mt = 0; mt < 2; mt++) {
            const float* p = smA + (wm * 32 + mt * 16 + g) * SA + ks * 8 + t;
            af[mt][0] = __float_as_uint(p[0]);
            af[mt][1] = __float_as_uint(p[8 * SA]);
            af[mt][2] = __float_as_uint(p[4]);
            af[mt][3] = __float_as_uint(p[8 * SA + 4]);
        }
#pragma unroll
        for (int nt = 0; nt < 8; nt++) {
            const float* q = smB + (wn * 64 + nt * 8 + g) * SA + ks * 8 + t;
            uint32_t bf[2];
            bf[0] = __float_as_uint(q[0]);
            bf[1] = __float_as_uint(q[4]);
#pragma unroll
            for (int mt = 0; mt < 2; mt++)
                mma_tf32(acc[mt][nt], af[mt], bf);
        }
    }
}

__global__ void __launch_bounds__(256) k_gates_mma(const float* __restrict__ Wih,
                                                   const float* __restrict__ m_i,
                                                   float* __restrict__ out) {
    extern __shared__ float sm[];
    int tid = threadIdx.x, lane = tid & 31, wid = tid >> 5;
    int wm = wid >> 1, wn = wid & 1;
    int b = blockIdx.x, m0 = b * 128, d0 = blockIdx.y * 32;

    float acc[2][8][4];
#pragma unroll
    for (int i = 0; i < 2; i++)
#pragma unroll
        for (int j = 0; j < 8; j++)
#pragma unroll
            for (int k = 0; k < 4; k++) acc[i][j][k] = 0.f;

    float* Abuf[2] = {sm, sm + 4608};
    float* Bbuf[2] = {sm + 9216, sm + 13824};

    float4 aR[4];
    float bR[16];
    g_ldA(aR, 0, m0, b, tid);
    g_ldB(bR, 0, d0, Wih, tid);
    g_stA(Abuf[0], aR, tid);
    g_stB(Bbuf[0], bR, tid);
    __syncthreads();

#pragma unroll 1
    for (int kt = 0; kt < NTK; kt++) {
        int cur = kt & 1;
        if (kt + 1 < NTK) {
            g_ldA(aR, kt + 1, m0, b, tid);
            g_ldB(bR, kt + 1, d0, Wih, tid);
        }
        g_compute(Abuf[cur], Bbuf[cur], acc, lane, wm, wn);
        if (kt + 1 < NTK) {
            g_stA(Abuf[cur ^ 1], aR, tid);
            g_stB(Bbuf[cur ^ 1], bR, tid);
        }
        __syncthreads();
    }

    float* stg = sm;
    int g = lane >> 2, t = lane & 3;
#pragma unroll
    for (int mt = 0; mt < 2; mt++) {
        int r0 = wm * 32 + mt * 16 + g;
#pragma unroll
        for (int nt = 0; nt < 8; nt++) {
            int c0 = wn * 64 + nt * 8 + 2 * t;
            stg[r0 * SSTG + c0]           = acc[mt][nt][0];
            stg[r0 * SSTG + c0 + 1]       = acc[mt][nt][1];
            stg[(r0 + 8) * SSTG + c0]     = acc[mt][nt][2];
            stg[(r0 + 8) * SSTG + c0 + 1] = acc[mt][nt][3];
        }
    }
    __syncthreads();
    int r = tid >> 1, h = tid & 1;
    const float* shp = g_sh + b * 4 * DHD;
    const float* mip = m_i + b * DHD;
#pragma unroll
    for (int j = 0; j < 16; j++) {
        int dd = h * 16 + j;
        int d = d0 + dd;
        float ig = stg[r * SSTG + dd]      + shp[d];
        float fg = stg[r * SSTG + 32 + dd] + shp[DHD + d];
        float gg = stg[r * SSTG + 64 + dd] + shp[2 * DHD + d];
        float og = stg[r * SSTG + 96 + dd] + shp[3 * DHD + d];
        float cnew = sigm(fg) * mip[d] + sigm(ig) * tanhf(gg);
        out[(size_t)(m0 + r) * DHD + d] = sigm(og) * tanhf(cnew);
    }
}

// ---------------- launch -----------------------------------------------------
extern "C" void kernel_launch(void* const* d_in, const int* in_sizes, int n_in,
                              void* d_out, int out_size) {
    const float* LSTM  = (const float*)d_in[0];
    const float* CNNs  = (const float*)d_in[1];
    const float* Wa_w  = (const float*)d_in[2];
    const float* Wa_b  = (const float*)d_in[3];
    const float* Ua_w  = (const float*)d_in[4];
    const float* Ua_b  = (const float*)d_in[5];
    const float* va_w  = (const float*)d_in[6];
    const float* va_b  = (const float*)d_in[7];
    const float* phi_w = (const float*)d_in[8];
    const float* phi_b = (const float*)d_in[9];
    const float* Wih   = (const float*)d_in[10];
    const float* Whh   = (const float*)d_in[11];
    const float* bih   = (const float*)d_in[12];
    const float* bhh   = (const float*)d_in[13];
    const float* wij_w = (const float*)d_in[14];
    const float* wij_b = (const float*)d_in[15];
    const float* s_i   = (const float*)d_in[16];
    const float* m_i   = (const float*)d_in[17];
    float* out = (float*)d_out;

    static int smem_set = 0;
    if (!smem_set) {
        cudaFuncSetAttribute(k_gates_mma,  cudaFuncAttributeMaxDynamicSharedMemorySize, SMEMG);
        cudaFuncSetAttribute(k_escore_mma, cudaFuncAttributeMaxDynamicSharedMemorySize, 73728);
        cudaFuncSetAttribute(k_av_mma,     cudaFuncAttributeMaxDynamicSharedMemorySize, 71680);
        smem_set = 1;
    }

    k_phi<<<EHD, TE>>>(phi_w, phi_b);
    k_prep<<<35, 256>>>(s_i, Wa_w, Wa_b, Whh, bhh, bih, wij_w, wij_b);
    k_cnn<<<1, 896>>>(CNNs, wij_w);
    k_escore_mma<<<dim3(8, 128), 256, 73728>>>(LSTM, Ua_w, Ua_b, va_w, va_b);
    k_softmax<<<BB * TD, 256>>>();
    k_av_mma<<<dim3(4, 128), 256, 71680>>>(LSTM);
    k_gates_mma<<<dim3(128, 16), 256, SMEMG>>>(Wih, m_i, out);
}

// round 7
// speedup vs baseline: 2.8463x; 1.1802x over previous
#include <cuda_runtime.h>
#include <cstdint>

#define BB 128
#define TE 512
#define TD 128
#define EHD 512
#define DHD 512
#define KC 7
#define CC 105
#define KW 617   // CC + DHD
#define KWP 640  // padded K for gates

// ---------------- scratch (device globals; no allocations allowed) -----------
__device__ float g_phi[TE * EHD];          // phi[t][e]
__device__ float g_Wa[BB * TD];            // Wa + Wa_b
__device__ float g_sh[BB * 4 * DHD];       // s_i@Whh.T + bhh + bih
__device__ float g_sdot[BB * KC];          // s_i@w_s.T + wij_b
__device__ float g_cp2[BB * 128];          // c_p zero-padded to 128
__device__ float g_E[BB * TD * TE];        // scores -> softmax in place
__device__ float g_ci[BB * TD * EHD];      // attention output
__device__ float g_Wp[4 * DHD * KWP];      // Wih repacked, zero-padded rows (aligned)

__device__ __forceinline__ float sigm(float x) { return 1.f / (1.f + __expf(-x)); }
__device__ __forceinline__ uint32_t smem_u32(const void* p) {
    uint32_t a;
    asm("{ .reg .u64 t; cvta.to.shared.u64 t, %1; cvt.u32.u64 %0, t; }" : "=r"(a) : "l"(p));
    return a;
}
__device__ __forceinline__ void cp16(uint32_t dst, const void* src) {
    asm volatile("cp.async.ca.shared.global [%0], [%1], 16;" :: "r"(dst), "l"(src));
}
__device__ __forceinline__ void cp16z(uint32_t dst, const void* src, int sz) {
    asm volatile("cp.async.ca.shared.global [%0], [%1], 16, %2;" :: "r"(dst), "l"(src), "r"(sz));
}
#define CP_COMMIT() asm volatile("cp.async.commit_group;" ::: "memory")
#define CP_WAIT1()  asm volatile("cp.async.wait_group 1;"  ::: "memory")
__device__ __forceinline__ void mma_tf32(float* d, const uint32_t* a, const uint32_t* b) {
    asm volatile("mma.sync.aligned.m16n8k8.row.col.f32.tf32.tf32.f32 "
                 "{%0,%1,%2,%3}, {%4,%5,%6,%7}, {%8,%9}, {%0,%1,%2,%3};"
                 : "+f"(d[0]), "+f"(d[1]), "+f"(d[2]), "+f"(d[3])
                 : "r"(a[0]), "r"(a[1]), "r"(a[2]), "r"(a[3]), "r"(b[0]), "r"(b[1]));
}

// ---------------- K0: repack Wih rows 617 -> 640 (aligned, zero-padded) ------
__global__ void k_packW(const float* __restrict__ Wih) {
    int n = blockIdx.x;
    const float* src = Wih + (size_t)n * KW;
    float* dst = g_Wp + (size_t)n * KWP;
    for (int k = threadIdx.x; k < KWP; k += 256)
        dst[k] = (k < KW) ? src[k] : 0.f;
}

// ---------------- K1: phi[t][e] = phi_b[e] + sum_{t'<t} phi_w[e][t'] ---------
__global__ void k_phi(const float* __restrict__ phi_w, const float* __restrict__ phi_b) {
    int e = blockIdx.x, t = threadIdx.x;
    __shared__ float s[2][TE];
    s[0][t] = phi_w[e * TE + t];
    __syncthreads();
    int src = 0;
    for (int off = 1; off < TE; off <<= 1) {
        float v = s[src][t];
        if (t >= off) v += s[src][t - off];
        s[src ^ 1][t] = v;
        __syncthreads();
        src ^= 1;
    }
    g_phi[t * EHD + e] = phi_b[e] + (t ? s[src][t - 1] : 0.f);
}

// ---------------- K2: fused small GEMM: C = s_i @ W.T for [Wa_w; Whh; w_s] ---
#define N2 2183   // 128 + 2048 + 7
__global__ void k_prep(const float* __restrict__ s_i,
                       const float* __restrict__ Wa_w, const float* __restrict__ Wa_b,
                       const float* __restrict__ Whh,  const float* __restrict__ bhh,
                       const float* __restrict__ bih,
                       const float* __restrict__ wij_w, const float* __restrict__ wij_b) {
    __shared__ float As[128][33];
    __shared__ float Ws[64][33];
    int tid = threadIdx.x;
    int tx = tid & 15, ty = tid >> 4;
    int n0 = blockIdx.x * 64;
    float acc[8][4];
#pragma unroll
    for (int a = 0; a < 8; a++)
#pragma unroll
        for (int c = 0; c < 4; c++) acc[a][c] = 0.f;

    for (int k0 = 0; k0 < DHD; k0 += 32) {
#pragma unroll
        for (int r = 0; r < 16; r++) {
            int lin = tid + 256 * r;
            int row = lin >> 5, kk = lin & 31;
            As[row][kk] = s_i[row * DHD + k0 + kk];
        }
#pragma unroll
        for (int r = 0; r < 8; r++) {
            int lin = tid + 256 * r;
            int col = lin >> 5, kk = lin & 31;
            int n = n0 + col, k = k0 + kk;
            float v = 0.f;
            if (n < TD)                 v = Wa_w[n * DHD + k];
            else if (n < TD + 4 * DHD)  v = Whh[(n - TD) * DHD + k];
            else if (n < N2)            v = wij_w[(n - TD - 4 * DHD) * KW + CC + k];
            Ws[col][kk] = v;
        }
        __syncthreads();
#pragma unroll
        for (int kk = 0; kk < 32; kk++) {
            float xv[8], wv[4];
#pragma unroll
            for (int jm = 0; jm < 8; jm++) xv[jm] = As[ty + 16 * jm][kk];
#pragma unroll
            for (int jn = 0; jn < 4; jn++) wv[jn] = Ws[tx + 16 * jn][kk];
#pragma unroll
            for (int jm = 0; jm < 8; jm++)
#pragma unroll
                for (int jn = 0; jn < 4; jn++) acc[jm][jn] += xv[jm] * wv[jn];
        }
        __syncthreads();
    }
#pragma unroll
    for (int jm = 0; jm < 8; jm++) {
        int m = ty + 16 * jm;
#pragma unroll
        for (int jn = 0; jn < 4; jn++) {
            int n = n0 + tx + 16 * jn;
            float v = acc[jm][jn];
            if (n < TD)                g_Wa[m * TD + n] = v + Wa_b[n];
            else if (n < TD + 4 * DHD) g_sh[m * 4 * DHD + (n - TD)] = v + bhh[n - TD] + bih[n - TD];
            else if (n < N2)           g_sdot[m * KC + (n - TD - 4 * DHD)] = v + wij_b[n - TD - 4 * DHD];
        }
    }
}

// ---------------- K3: CNN path: ep, global-scalar-normalized ap, c_p ---------
__global__ void k_cnn(const float* __restrict__ CNNs, const float* __restrict__ wij_w) {
    __shared__ float ep_s[BB * KC];
    __shared__ float red[32];
    __shared__ float Ssh;
    int tid = threadIdx.x;     // 896 threads, one per (b,k)
    int k = tid % KC;
    float acc = g_sdot[tid];
    const float* crow = CNNs + tid * CC;
    const float* wrow = wij_w + k * KW;
#pragma unroll 5
    for (int c = 0; c < CC; c++) acc += crow[c] * wrow[c];
    float epv = tanhf(acc);

    float v = epv;
#pragma unroll
    for (int o = 16; o; o >>= 1) v += __shfl_xor_sync(0xffffffffu, v, o);
    if ((tid & 31) == 0) red[tid >> 5] = v;
    __syncthreads();
    if (tid == 0) {
        float s = 0.f;
        for (int w = 0; w < 28; w++) s += red[w];
        Ssh = s;            // NOTE: reference divides by sum of ep (not exp(ep))
    }
    __syncthreads();
    ep_s[tid] = __expf(epv) / Ssh;
    __syncthreads();
    for (int o = tid; o < BB * 128; o += 896) {
        int b = o >> 7, c = o & 127;
        float s = 0.f;
        if (c < CC) {
#pragma unroll
            for (int kk = 0; kk < KC; kk++)
                s += ep_s[b * KC + kk] * CNNs[(b * KC + kk) * CC + c];
        }
        g_cp2[o] = s;
    }
}

// ========== K4: banded score GEMM via mma.sync tf32 + cp.async pipeline ======
// Per CTA: b, 64 t's.  C[tt][s'] = sum_k P[t0+tt][k] * Ua_w[s_lo+s'][k], s' in 0..191.
#define ES_STG 36864   // bytes per stage: A 64x36 f32 (9216) + B 192x36 f32 (27648)
__global__ void __launch_bounds__(256) k_escore_mma(const float* __restrict__ LSTM,
                                                    const float* __restrict__ Ua_w,
                                                    const float* __restrict__ Ua_b,
                                                    const float* __restrict__ va_w,
                                                    const float* __restrict__ va_b) {
    extern __shared__ float sm[];
    uint32_t smb = smem_u32(sm);
    int tid = threadIdx.x, lane = tid & 31, wid = tid >> 5;
    int g = lane >> 2, t = lane & 3;
    int wm = wid & 1, wn = wid >> 1;           // 2 x 4 warp grid
    int t0 = blockIdx.x * 64, b = blockIdx.y;
    int s_lo = 321 - t0;
    const float* Lb = LSTM + (size_t)b * TE * EHD;

    float acc[2][6][4];
#pragma unroll
    for (int i = 0; i < 2; i++)
#pragma unroll
        for (int j = 0; j < 6; j++)
#pragma unroll
            for (int k = 0; k < 4; k++) acc[i][j][k] = 0.f;

    auto issueB = [&](int kt) {
        uint32_t base = smb + (kt % 3) * ES_STG + 9216;
#pragma unroll
        for (int r = 0; r < 6; r++) {
            int lin = tid + 256 * r;
            int c = lin >> 3, q = lin & 7;
            int s = s_lo + c;
            int sc = s < 0 ? 0 : (s > 511 ? 511 : s);
            cp16z(base + (c * 36 + 4 * q) * 4,
                  Ua_w + (size_t)sc * EHD + kt * 32 + 4 * q,
                  ((unsigned)s < 512u) ? 16 : 0);
        }
    };
    auto ldstA = [&](int kt) {
        float* A = sm + (kt % 3) * (ES_STG / 4);
#pragma unroll
        for (int r = 0; r < 2; r++) {
            int lin = tid + 256 * r;
            int row = lin >> 3, q = lin & 7;
            int off = (t0 + row) * EHD + kt * 32 + 4 * q;
            float4 p = *(const float4*)(g_phi + off);
            float4 l = *(const float4*)(Lb + off);
            float4 o = {p.x * l.x, p.y * l.y, p.z * l.z, p.w * l.w};
            *(float4*)(A + row * 36 + 4 * q) = o;
        }
    };
    auto comp = [&](int kt) {
        const float* A = sm + (kt % 3) * (ES_STG / 4);
        const float* B = A + 2304;
#pragma unroll
        for (int ks = 0; ks < 4; ks++) {
            uint32_t af[2][4];
#pragma unroll
            for (int mt = 0; mt < 2; mt++) {
                const float* p = A + (wm * 32 + mt * 16 + g) * 36 + ks * 8 + t;
                af[mt][0] = __float_as_uint(p[0]);
                af[mt][1] = __float_as_uint(p[8 * 36]);
                af[mt][2] = __float_as_uint(p[4]);
                af[mt][3] = __float_as_uint(p[8 * 36 + 4]);
            }
#pragma unroll
            for (int nt = 0; nt < 6; nt++) {
                const float* q2 = B + (wn * 48 + nt * 8 + g) * 36 + ks * 8 + t;
                uint32_t bf[2] = {__float_as_uint(q2[0]), __float_as_uint(q2[4])};
                mma_tf32(acc[0][nt], af[0], bf);
                mma_tf32(acc[1][nt], af[1], bf);
            }
        }
    };

    issueB(0); CP_COMMIT(); ldstA(0);
    issueB(1); CP_COMMIT(); ldstA(1);
#pragma unroll 1
    for (int kt = 0; kt < 16; kt++) {
        CP_WAIT1();
        __syncthreads();
        if (kt + 2 < 16) { issueB(kt + 2); CP_COMMIT(); ldstA(kt + 2); }
        comp(kt);
    }
    __syncthreads();

    // stage C [64][192] to smem (stride 196), then band epilogue
    float* stg = sm;
#pragma unroll
    for (int mt = 0; mt < 2; mt++) {
        int r0 = wm * 32 + mt * 16 + g;
#pragma unroll
        for (int nt = 0; nt < 6; nt++) {
            int c0 = wn * 48 + nt * 8 + 2 * t;
            stg[r0 * 196 + c0]           = acc[mt][nt][0];
            stg[r0 * 196 + c0 + 1]       = acc[mt][nt][1];
            stg[(r0 + 8) * 196 + c0]     = acc[mt][nt][2];
            stg[(r0 + 8) * 196 + c0 + 1] = acc[mt][nt][3];
        }
    }
    __syncthreads();
    float vb = va_b[0];
#pragma unroll 1
    for (int r = 0; r < 32; r++) {
        int lin = tid + 256 * r;
        int tt = lin & 63, ii = lin >> 6;
        int sp = ii - tt + 63;
        int s = s_lo + sp;
        int jc = s + 128;
        float ev;
        if (s >= 0) ev = tanhf(stg[tt * 196 + sp] + Ua_b[s]) * va_w[jc] + vb;
        else        ev = tanhf(g_Wa[b * TD + jc]) * va_w[jc] + vb;
        g_E[((size_t)(b * TD + ii)) * TE + t0 + tt] = ev;
    }
}

// ---------------- K5: row softmax over t (in place on g_E) -------------------
__global__ void k_softmax() {
    int row = blockIdx.x;
    float* p = g_E + row * TE;
    int tid = threadIdx.x;   // 256
    __shared__ float red[8], red2[8];
    float v0 = p[tid], v1 = p[tid + 256];
    float m = fmaxf(v0, v1);
#pragma unroll
    for (int o = 16; o; o >>= 1) m = fmaxf(m, __shfl_xor_sync(0xffffffffu, m, o));
    if ((tid & 31) == 0) red[tid >> 5] = m;
    __syncthreads();
    if (tid == 0) {
        float mm = red[0];
        for (int w = 1; w < 8; w++) mm = fmaxf(mm, red[w]);
        red[0] = mm;
    }
    __syncthreads();
    float M = red[0];
    float e0 = __expf(v0 - M), e1 = __expf(v1 - M);
    float s = e0 + e1;
#pragma unroll
    for (int o = 16; o; o >>= 1) s += __shfl_xor_sync(0xffffffffu, s, o);
    if ((tid & 31) == 0) red2[tid >> 5] = s;
    __syncthreads();
    if (tid == 0) {
        float ss = 0.f;
        for (int w = 0; w < 8; w++) ss += red2[w];
        red2[0] = ss;
    }
    __syncthreads();
    float inv = 1.f / red2[0];
    p[tid] = e0 * inv;
    p[tid + 256] = e1 * inv;
}

// ========== K6: c_i[b] = a[b] @ LSTM[b] via mma.sync tf32 + cp.async =========
// Per CTA: b, 128 e's.  M=128(i), N=128(e), K=512(t).  B staged k-major, stride 136.
#define AV_STG 35840   // A 128x36 f32 (18432) + B 32x136 f32 (17408)
__global__ void __launch_bounds__(256) k_av_mma(const float* __restrict__ LSTM) {
    extern __shared__ float sm[];
    uint32_t smb = smem_u32(sm);
    int tid = threadIdx.x, lane = tid & 31, wid = tid >> 5;
    int g = lane >> 2, t = lane & 3;
    int wm = wid >> 1, wn = wid & 1;   // 4 x 2 warp grid
    int e0 = blockIdx.x * 128, b = blockIdx.y;
    const float* Lb = LSTM + (size_t)b * TE * EHD;
    const float* Ag = g_E + (size_t)b * TD * TE;

    float acc[2][8][4];
#pragma unroll
    for (int i = 0; i < 2; i++)
#pragma unroll
        for (int j = 0; j < 8; j++)
#pragma unroll
            for (int k = 0; k < 4; k++) acc[i][j][k] = 0.f;

    auto issue = [&](int kt) {
        uint32_t base = smb + (kt % 3) * AV_STG;
#pragma unroll
        for (int r = 0; r < 4; r++) {   // A: 128 rows x 8 chunks
            int lin = tid + 256 * r;
            int row = lin >> 3, q = lin & 7;
            cp16(base + (row * 36 + 4 * q) * 4,
                 Ag + (size_t)row * TE + kt * 32 + 4 * q);
        }
#pragma unroll
        for (int r = 0; r < 4; r++) {   // B: 32 k x 32 chunks (k-major)
            int lin = tid + 256 * r;
            int kk = lin >> 5, cq = lin & 31;
            cp16(base + 18432 + (kk * 136 + 4 * cq) * 4,
                 Lb + (size_t)(kt * 32 + kk) * EHD + e0 + 4 * cq);
        }
    };
    auto comp = [&](int kt) {
        const float* A = sm + (kt % 3) * (AV_STG / 4);
        const float* B = A + 4608;
#pragma unroll
        for (int ks = 0; ks < 4; ks++) {
            uint32_t af[2][4];
#pragma unroll
            for (int mt = 0; mt < 2; mt++) {
                const float* p = A + (wm * 32 + mt * 16 + g) * 36 + ks * 8 + t;
                af[mt][0] = __float_as_uint(p[0]);
                af[mt][1] = __float_as_uint(p[8 * 36]);
                af[mt][2] = __float_as_uint(p[4]);
                af[mt][3] = __float_as_uint(p[8 * 36 + 4]);
            }
            int kb = ks * 8 + t;
#pragma unroll
            for (int nt = 0; nt < 8; nt++) {
                int c0 = wn * 64 + nt * 8 + g;
                uint32_t bf[2] = {__float_as_uint(B[kb * 136 + c0]),
                                  __float_as_uint(B[(kb + 4) * 136 + c0])};
                mma_tf32(acc[0][nt], af[0], bf);
                mma_tf32(acc[1][nt], af[1], bf);
            }
        }
    };

    issue(0); CP_COMMIT();
    issue(1); CP_COMMIT();
#pragma unroll 1
    for (int kt = 0; kt < 16; kt++) {
        CP_WAIT1();
        __syncthreads();
        if (kt + 2 < 16) { issue(kt + 2); CP_COMMIT(); }
        comp(kt);
    }

    // direct epilogue: each 4-lane quad writes full 32B sectors of g_ci
#pragma unroll
    for (int mt = 0; mt < 2; mt++) {
        int r0 = wm * 32 + mt * 16 + g;
#pragma unroll
        for (int nt = 0; nt < 8; nt++) {
            int c = e0 + wn * 64 + nt * 8 + 2 * t;
            *(float2*)(g_ci + (size_t)(b * TD + r0) * EHD + c) =
                make_float2(acc[mt][nt][0], acc[mt][nt][1]);
            *(float2*)(g_ci + (size_t)(b * TD + r0 + 8) * EHD + c) =
                make_float2(acc[mt][nt][2], acc[mt][nt][3]);
        }
    }
}

// ======== K7: gates GEMM via mma.sync tf32 + cp.async + fused LSTM cell ======
#define NTK 20
#define GA_STG 36864   // A 128x36 f32 (18432) + B 128x36 f32 (18432)
#define SSTG 132
#define SMEMG (3 * GA_STG)
__global__ void __launch_bounds__(256) k_gates_mma(const float* __restrict__ m_i,
                                                   float* __restrict__ out) {
    extern __shared__ float sm[];
    uint32_t smb = smem_u32(sm);
    int tid = threadIdx.x, lane = tid & 31, wid = tid >> 5;
    int g = lane >> 2, t = lane & 3;
    int wm = wid >> 1, wn = wid & 1;
    int b = blockIdx.x, m0 = b * 128, d0 = blockIdx.y * 32;

    float acc[2][8][4];
#pragma unroll
    for (int i = 0; i < 2; i++)
#pragma unroll
        for (int j = 0; j < 8; j++)
#pragma unroll
            for (int k = 0; k < 4; k++) acc[i][j][k] = 0.f;

    auto issue = [&](int kt) {
        uint32_t base = smb + (kt % 3) * GA_STG;
#pragma unroll
        for (int r = 0; r < 4; r++) {   // A: 128 rows x 8 chunks
            int lin = tid + 256 * r;
            int row = lin >> 3, q = lin & 7;
            const float* src = (kt < 16)
                ? g_ci + (size_t)(m0 + row) * EHD + kt * 32 + 4 * q
                : g_cp2 + b * 128 + (kt - 16) * 32 + 4 * q;
            cp16(base + (row * 36 + 4 * q) * 4, src);
        }
#pragma unroll
        for (int r = 0; r < 4; r++) {   // B: 128 cols x 8 chunks (from padded g_Wp)
            int lin = tid + 256 * r;
            int c = lin >> 3, q = lin & 7;
            int n = ((c >> 5) << 9) + d0 + (c & 31);
            cp16(base + 18432 + (c * 36 + 4 * q) * 4,
                 g_Wp + (size_t)n * KWP + kt * 32 + 4 * q);
        }
    };
    auto comp = [&](int kt) {
        const float* A = sm + (kt % 3) * (GA_STG / 4);
        const float* B = A + 4608;
#pragma unroll
        for (int ks = 0; ks < 4; ks++) {
            uint32_t af[2][4];
#pragma unroll
            for (int mt = 0; mt < 2; mt++) {
                const float* p = A + (wm * 32 + mt * 16 + g) * 36 + ks * 8 + t;
                af[mt][0] = __float_as_uint(p[0]);
                af[mt][1] = __float_as_uint(p[8 * 36]);
                af[mt][2] = __float_as_uint(p[4]);
                af[mt][3] = __float_as_uint(p[8 * 36 + 4]);
            }
#pragma unroll
            for (int nt = 0; nt < 8; nt++) {
                const float* q2 = B + (wn * 64 + nt * 8 + g) * 36 + ks * 8 + t;
                uint32_t bf[2] = {__float_as_uint(q2[0]), __float_as_uint(q2[4])};
                mma_tf32(acc[0][nt], af[0], bf);
                mma_tf32(acc[1][nt], af[1], bf);
            }
        }
    };

    issue(0); CP_COMMIT();
    issue(1); CP_COMMIT();
#pragma unroll 1
    for (int kt = 0; kt < NTK; kt++) {
        CP_WAIT1();
        __syncthreads();
        if (kt + 2 < NTK) { issue(kt + 2); CP_COMMIT(); }
        comp(kt);
    }
    __syncthreads();

    float* stg = sm;
#pragma unroll
    for (int mt = 0; mt < 2; mt++) {
        int r0 = wm * 32 + mt * 16 + g;
#pragma unroll
        for (int nt = 0; nt < 8; nt++) {
            int c0 = wn * 64 + nt * 8 + 2 * t;
            stg[r0 * SSTG + c0]           = acc[mt][nt][0];
            stg[r0 * SSTG + c0 + 1]       = acc[mt][nt][1];
            stg[(r0 + 8) * SSTG + c0]     = acc[mt][nt][2];
            stg[(r0 + 8) * SSTG + c0 + 1] = acc[mt][nt][3];
        }
    }
    __syncthreads();
    int r = tid >> 1, h = tid & 1;
    const float* shp = g_sh + b * 4 * DHD;
    const float* mip = m_i + b * DHD;
#pragma unroll
    for (int j = 0; j < 16; j++) {
        int dd = h * 16 + j;
        int d = d0 + dd;
        float ig = stg[r * SSTG + dd]      + shp[d];
        float fg = stg[r * SSTG + 32 + dd] + shp[DHD + d];
        float gg = stg[r * SSTG + 64 + dd] + shp[2 * DHD + d];
        float og = stg[r * SSTG + 96 + dd] + shp[3 * DHD + d];
        float cnew = sigm(fg) * mip[d] + sigm(ig) * tanhf(gg);
        out[(size_t)(m0 + r) * DHD + d] = sigm(og) * tanhf(cnew);
    }
}

// ---------------- launch -----------------------------------------------------
extern "C" void kernel_launch(void* const* d_in, const int* in_sizes, int n_in,
                              void* d_out, int out_size) {
    const float* LSTM  = (const float*)d_in[0];
    const float* CNNs  = (const float*)d_in[1];
    const float* Wa_w  = (const float*)d_in[2];
    const float* Wa_b  = (const float*)d_in[3];
    const float* Ua_w  = (const float*)d_in[4];
    const float* Ua_b  = (const float*)d_in[5];
    const float* va_w  = (const float*)d_in[6];
    const float* va_b  = (const float*)d_in[7];
    const float* phi_w = (const float*)d_in[8];
    const float* phi_b = (const float*)d_in[9];
    const float* Wih   = (const float*)d_in[10];
    const float* Whh   = (const float*)d_in[11];
    const float* bih   = (const float*)d_in[12];
    const float* bhh   = (const float*)d_in[13];
    const float* wij_w = (const float*)d_in[14];
    const float* wij_b = (const float*)d_in[15];
    const float* s_i   = (const float*)d_in[16];
    const float* m_i   = (const float*)d_in[17];
    float* out = (float*)d_out;

    static int smem_set = 0;
    if (!smem_set) {
        cudaFuncSetAttribute(k_gates_mma,  cudaFuncAttributeMaxDynamicSharedMemorySize, SMEMG);
        cudaFuncSetAttribute(k_escore_mma, cudaFuncAttributeMaxDynamicSharedMemorySize, 3 * ES_STG);
        cudaFuncSetAttribute(k_av_mma,     cudaFuncAttributeMaxDynamicSharedMemorySize, 3 * AV_STG);
        smem_set = 1;
    }

    k_packW<<<4 * DHD, 256>>>(Wih);
    k_phi<<<EHD, TE>>>(phi_w, phi_b);
    k_prep<<<35, 256>>>(s_i, Wa_w, Wa_b, Whh, bhh, bih, wij_w, wij_b);
    k_cnn<<<1, 896>>>(CNNs, wij_w);
    k_escore_mma<<<dim3(8, 128), 256, 3 * ES_STG>>>(LSTM, Ua_w, Ua_b, va_w, va_b);
    k_softmax<<<BB * TD, 256>>>();
    k_av_mma<<<dim3(4, 128), 256, 3 * AV_STG>>>(LSTM);
    k_gates_mma<<<dim3(128, 16), 256, SMEMG>>>(m_i, out);
}

// round 9
// speedup vs baseline: 2.8703x; 1.0084x over previous
#include <cuda_runtime.h>
#include <cstdint>

#define BB 128
#define TE 512
#define TD 128
#define EHD 512
#define DHD 512
#define KC 7
#define CC 105
#define KW 617   // CC + DHD
#define KWP 640  // padded K for gates

// ---------------- scratch (device globals; no allocations allowed) -----------
__device__ float g_phi[TE * EHD];          // phi[t][e]
__device__ float g_Wa[BB * TD];            // Wa + Wa_b
__device__ float g_sh[BB * 4 * DHD];       // s_i@Whh.T + bhh + bih
__device__ float g_sdot[BB * KC];          // s_i@w_s.T + wij_b
__device__ float g_ep[BB * KC];            // tanh(ep)
__device__ float g_apv[BB * KC];           // exp(ep)/S
__device__ float g_cp2[BB * 128];          // c_p zero-padded to 128
__device__ float g_E[BB * TD * TE];        // scores -> softmax in place
__device__ float g_ci[BB * TD * EHD];      // attention output
__device__ float g_Wp[4 * DHD * KWP];      // Wih repacked, zero-padded rows (aligned)

__device__ __forceinline__ float sigm(float x) { return 1.f / (1.f + __expf(-x)); }
__device__ __forceinline__ uint32_t smem_u32(const void* p) {
    uint32_t a;
    asm("{ .reg .u64 t; cvta.to.shared.u64 t, %1; cvt.u32.u64 %0, t; }" : "=r"(a) : "l"(p));
    return a;
}
__device__ __forceinline__ void cp16(uint32_t dst, const void* src) {
    asm volatile("cp.async.ca.shared.global [%0], [%1], 16;" :: "r"(dst), "l"(src));
}
__device__ __forceinline__ void cp16z(uint32_t dst, const void* src, int sz) {
    asm volatile("cp.async.ca.shared.global [%0], [%1], 16, %2;" :: "r"(dst), "l"(src), "r"(sz));
}
#define CP_COMMIT() asm volatile("cp.async.commit_group;" ::: "memory")
#define CP_WAIT1()  asm volatile("cp.async.wait_group 1;"  ::: "memory")
__device__ __forceinline__ void mma_tf32(float* d, const uint32_t* a, const uint32_t* b) {
    asm volatile("mma.sync.aligned.m16n8k8.row.col.f32.tf32.tf32.f32 "
                 "{%0,%1,%2,%3}, {%4,%5,%6,%7}, {%8,%9}, {%0,%1,%2,%3};"
                 : "+f"(d[0]), "+f"(d[1]), "+f"(d[2]), "+f"(d[3])
                 : "r"(a[0]), "r"(a[1]), "r"(a[2]), "r"(a[3]), "r"(b[0]), "r"(b[1]));
}

// ---------------- K0: repack Wih rows 617 -> 640 (aligned, zero-padded) ------
__global__ void k_packW(const float* __restrict__ Wih) {
    int n = blockIdx.x;
    const float* src = Wih + (size_t)n * KW;
    float* dst = g_Wp + (size_t)n * KWP;
    for (int k = threadIdx.x; k < KWP; k += 256)
        dst[k] = (k < KW) ? src[k] : 0.f;
}

// ---------------- K1: phi scan, warp-per-column + coalesced transpose write --
#define PHI_E 16
__global__ void __launch_bounds__(512) k_phi(const float* __restrict__ phi_w,
                                             const float* __restrict__ phi_b) {
    __shared__ float smt[TE][PHI_E + 1];
    int wid = threadIdx.x >> 5, lane = threadIdx.x & 31;
    int e = blockIdx.x * PHI_E + wid;
    const float* src = phi_w + (size_t)e * TE;
    float pb = phi_b[e];
    float carry = 0.f;
#pragma unroll 1
    for (int i = 0; i < 16; i++) {
        int t = 32 * i + lane;
        float v = src[t];
        float x = v;
#pragma unroll
        for (int o = 1; o < 32; o <<= 1) {
            float y = __shfl_up_sync(0xffffffffu, x, o);
            if (lane >= o) x += y;
        }
        smt[t][wid] = pb + carry + x - v;   // exclusive prefix
        carry += __shfl_sync(0xffffffffu, x, 31);
    }
    __syncthreads();
    int e0 = blockIdx.x * PHI_E;
#pragma unroll 1
    for (int idx = threadIdx.x; idx < TE * PHI_E; idx += 512) {
        int t = idx >> 4, el = idx & 15;
        g_phi[t * EHD + e0 + el] = smt[t][el];
    }
}

// ---------------- K2: fused small GEMM: C = s_i @ W.T for [Wa_w; Whh; w_s] ---
#define N2 2183   // 128 + 2048 + 7
__global__ void k_prep(const float* __restrict__ s_i,
                       const float* __restrict__ Wa_w, const float* __restrict__ Wa_b,
                       const float* __restrict__ Whh,  const float* __restrict__ bhh,
                       const float* __restrict__ bih,
                       const float* __restrict__ wij_w, const float* __restrict__ wij_b) {
    __shared__ float As[128][33];
    __shared__ float Ws[64][33];
    int tid = threadIdx.x;
    int tx = tid & 15, ty = tid >> 4;
    int n0 = blockIdx.x * 64;
    float acc[8][4];
#pragma unroll
    for (int a = 0; a < 8; a++)
#pragma unroll
        for (int c = 0; c < 4; c++) acc[a][c] = 0.f;

    for (int k0 = 0; k0 < DHD; k0 += 32) {
#pragma unroll
        for (int r = 0; r < 16; r++) {
            int lin = tid + 256 * r;
            int row = lin >> 5, kk = lin & 31;
            As[row][kk] = s_i[row * DHD + k0 + kk];
        }
#pragma unroll
        for (int r = 0; r < 8; r++) {
            int lin = tid + 256 * r;
            int col = lin >> 5, kk = lin & 31;
            int n = n0 + col, k = k0 + kk;
            float v = 0.f;
            if (n < TD)                 v = Wa_w[n * DHD + k];
            else if (n < TD + 4 * DHD)  v = Whh[(n - TD) * DHD + k];
            else if (n < N2)            v = wij_w[(n - TD - 4 * DHD) * KW + CC + k];
            Ws[col][kk] = v;
        }
        __syncthreads();
#pragma unroll
        for (int kk = 0; kk < 32; kk++) {
            float xv[8], wv[4];
#pragma unroll
            for (int jm = 0; jm < 8; jm++) xv[jm] = As[ty + 16 * jm][kk];
#pragma unroll
            for (int jn = 0; jn < 4; jn++) wv[jn] = Ws[tx + 16 * jn][kk];
#pragma unroll
            for (int jm = 0; jm < 8; jm++)
#pragma unroll
                for (int jn = 0; jn < 4; jn++) acc[jm][jn] += xv[jm] * wv[jn];
        }
        __syncthreads();
    }
#pragma unroll
    for (int jm = 0; jm < 8; jm++) {
        int m = ty + 16 * jm;
#pragma unroll
        for (int jn = 0; jn < 4; jn++) {
            int n = n0 + tx + 16 * jn;
            float v = acc[jm][jn];
            if (n < TD)                g_Wa[m * TD + n] = v + Wa_b[n];
            else if (n < TD + 4 * DHD) g_sh[m * 4 * DHD + (n - TD)] = v + bhh[n - TD] + bih[n - TD];
            else if (n < N2)           g_sdot[m * KC + (n - TD - 4 * DHD)] = v + wij_b[n - TD - 4 * DHD];
        }
    }
}

// ---------------- K3a/b/c: CNN path, parallelized ----------------------------
__global__ void k_cnn_ep(const float* __restrict__ CNNs, const float* __restrict__ wij_w) {
    int b = blockIdx.x;
    int wid = threadIdx.x >> 5, lane = threadIdx.x & 31;   // 7 warps, warp = k
    const float* crow = CNNs + (size_t)(b * KC + wid) * CC;
    const float* wrow = wij_w + (size_t)wid * KW;
    float acc = 0.f;
#pragma unroll 1
    for (int c = lane; c < CC; c += 32) acc += crow[c] * wrow[c];
#pragma unroll
    for (int o = 16; o; o >>= 1) acc += __shfl_xor_sync(0xffffffffu, acc, o);
    if (lane == 0) g_ep[b * KC + wid] = tanhf(acc + g_sdot[b * KC + wid]);
}
__global__ void k_cnn_ap() {
    __shared__ float red[28];
    __shared__ float Ssh;
    int tid = threadIdx.x;   // 896
    float e = g_ep[tid];
    float v = e;
#pragma unroll
    for (int o = 16; o; o >>= 1) v += __shfl_xor_sync(0xffffffffu, v, o);
    if ((tid & 31) == 0) red[tid >> 5] = v;
    __syncthreads();
    if (tid == 0) {
        float s = 0.f;
        for (int w = 0; w < 28; w++) s += red[w];
        Ssh = s;            // reference divides by sum of ep (not exp(ep))
    }
    __syncthreads();
    g_apv[tid] = __expf(e) / Ssh;
}
__global__ void k_cnn_cp(const float* __restrict__ CNNs) {
    int b = blockIdx.x, c = threadIdx.x;   // 128 threads
    __shared__ float ap[KC];
    if (c < KC) ap[c] = g_apv[b * KC + c];
    __syncthreads();
    float s = 0.f;
    if (c < CC) {
#pragma unroll
        for (int k = 0; k < KC; k++)
            s += ap[k] * CNNs[(size_t)(b * KC + k) * CC + c];
    }
    g_cp2[b * 128 + c] = s;
}

// ========== K4: banded score GEMM via mma.sync tf32 + cp.async pipeline ======
#define ES_STG 36864   // bytes per stage: A 64x36 f32 (9216) + B 192x36 f32 (27648)
__global__ void __launch_bounds__(256) k_escore_mma(const float* __restrict__ LSTM,
                                                    const float* __restrict__ Ua_w,
                                                    const float* __restrict__ Ua_b,
                                                    const float* __restrict__ va_w,
                                                    const float* __restrict__ va_b) {
    extern __shared__ float sm[];
    uint32_t smb = smem_u32(sm);
    int tid = threadIdx.x, lane = tid & 31, wid = tid >> 5;
    int g = lane >> 2, t = lane & 3;
    int wm = wid & 1, wn = wid >> 1;           // 2 x 4 warp grid
    int t0 = blockIdx.x * 64, b = blockIdx.y;
    int s_lo = 321 - t0;
    const float* Lb = LSTM + (size_t)b * TE * EHD;

    float acc[2][6][4];
#pragma unroll
    for (int i = 0; i < 2; i++)
#pragma unroll
        for (int j = 0; j < 6; j++)
#pragma unroll
            for (int k = 0; k < 4; k++) acc[i][j][k] = 0.f;

    auto issueB = [&](int kt) {
        uint32_t base = smb + (kt % 3) * ES_STG + 9216;
#pragma unroll
        for (int r = 0; r < 6; r++) {
            int lin = tid + 256 * r;
            int c = lin >> 3, q = lin & 7;
            int s = s_lo + c;
            int sc = s < 0 ? 0 : (s > 511 ? 511 : s);
            cp16z(base + (c * 36 + 4 * q) * 4,
                  Ua_w + (size_t)sc * EHD + kt * 32 + 4 * q,
                  ((unsigned)s < 512u) ? 16 : 0);
        }
    };
    auto ldstA = [&](int kt) {
        float* A = sm + (kt % 3) * (ES_STG / 4);
#pragma unroll
        for (int r = 0; r < 2; r++) {
            int lin = tid + 256 * r;
            int row = lin >> 3, q = lin & 7;
            int off = (t0 + row) * EHD + kt * 32 + 4 * q;
            float4 p = *(const float4*)(g_phi + off);
            float4 l = *(const float4*)(Lb + off);
            float4 o = {p.x * l.x, p.y * l.y, p.z * l.z, p.w * l.w};
            *(float4*)(A + row * 36 + 4 * q) = o;
        }
    };
    auto comp = [&](int kt) {
        const float* A = sm + (kt % 3) * (ES_STG / 4);
        const float* B = A + 2304;
#pragma unroll
        for (int ks = 0; ks < 4; ks++) {
            uint32_t af[2][4];
#pragma unroll
            for (int mt = 0; mt < 2; mt++) {
                const float* p = A + (wm * 32 + mt * 16 + g) * 36 + ks * 8 + t;
                af[mt][0] = __float_as_uint(p[0]);
                af[mt][1] = __float_as_uint(p[8 * 36]);
                af[mt][2] = __float_as_uint(p[4]);
                af[mt][3] = __float_as_uint(p[8 * 36 + 4]);
            }
#pragma unroll
            for (int nt = 0; nt < 6; nt++) {
                const float* q2 = B + (wn * 48 + nt * 8 + g) * 36 + ks * 8 + t;
                uint32_t bf[2] = {__float_as_uint(q2[0]), __float_as_uint(q2[4])};
                mma_tf32(acc[0][nt], af[0], bf);
                mma_tf32(acc[1][nt], af[1], bf);
            }
        }
    };

    issueB(0); CP_COMMIT(); ldstA(0);
    issueB(1); CP_COMMIT(); ldstA(1);
#pragma unroll 1
    for (int kt = 0; kt < 16; kt++) {
        CP_WAIT1();
        __syncthreads();
        if (kt + 2 < 16) { issueB(kt + 2); CP_COMMIT(); ldstA(kt + 2); }
        comp(kt);
    }
    __syncthreads();

    // stage C [64][192] to smem (stride 196), then band epilogue
    float* stg = sm;
#pragma unroll
    for (int mt = 0; mt < 2; mt++) {
        int r0 = wm * 32 + mt * 16 + g;
#pragma unroll
        for (int nt = 0; nt < 6; nt++) {
            int c0 = wn * 48 + nt * 8 + 2 * t;
            stg[r0 * 196 + c0]           = acc[mt][nt][0];
            stg[r0 * 196 + c0 + 1]       = acc[mt][nt][1];
            stg[(r0 + 8) * 196 + c0]     = acc[mt][nt][2];
            stg[(r0 + 8) * 196 + c0 + 1] = acc[mt][nt][3];
        }
    }
    __syncthreads();
    float vb = va_b[0];
#pragma unroll 1
    for (int r = 0; r < 32; r++) {
        int lin = tid + 256 * r;
        int tt = lin & 63, ii = lin >> 6;
        int sp = ii - tt + 63;
        int s = s_lo + sp;
        int jc = s + 128;
        float ev;
        if (s >= 0) ev = tanhf(stg[tt * 196 + sp] + Ua_b[s]) * va_w[jc] + vb;
        else        ev = tanhf(g_Wa[b * TD + jc]) * va_w[jc] + vb;
        g_E[((size_t)(b * TD + ii)) * TE + t0 + tt] = ev;
    }
}

// ---------------- K5: row softmax over t (in place on g_E) -------------------
__global__ void k_softmax() {
    int row = blockIdx.x;
    float* p = g_E + row * TE;
    int tid = threadIdx.x;   // 256
    __shared__ float red[8], red2[8];
    float v0 = p[tid], v1 = p[tid + 256];
    float m = fmaxf(v0, v1);
#pragma unroll
    for (int o = 16; o; o >>= 1) m = fmaxf(m, __shfl_xor_sync(0xffffffffu, m, o));
    if ((tid & 31) == 0) red[tid >> 5] = m;
    __syncthreads();
    if (tid == 0) {
        float mm = red[0];
        for (int w = 1; w < 8; w++) mm = fmaxf(mm, red[w]);
        red[0] = mm;
    }
    __syncthreads();
    float M = red[0];
    float e0 = __expf(v0 - M), e1 = __expf(v1 - M);
    float s = e0 + e1;
#pragma unroll
    for (int o = 16; o; o >>= 1) s += __shfl_xor_sync(0xffffffffu, s, o);
    if ((tid & 31) == 0) red2[tid >> 5] = s;
    __syncthreads();
    if (tid == 0) {
        float ss = 0.f;
        for (int w = 0; w < 8; w++) ss += red2[w];
        red2[0] = ss;
    }
    __syncthreads();
    float inv = 1.f / red2[0];
    p[tid] = e0 * inv;
    p[tid + 256] = e1 * inv;
}

// ========== K6: c_i[b] = a[b] @ LSTM[b] via mma.sync tf32 + cp.async =========
#define AV_STG 35840   // A 128x36 f32 (18432) + B 32x136 f32 (17408)
__global__ void __launch_bounds__(256) k_av_mma(const float* __restrict__ LSTM) {
    extern __shared__ float sm[];
    uint32_t smb = smem_u32(sm);
    int tid = threadIdx.x, lane = tid & 31, wid = tid >> 5;
    int g = lane >> 2, t = lane & 3;
    int wm = wid >> 1, wn = wid & 1;   // 4 x 2 warp grid
    int e0 = blockIdx.x * 128, b = blockIdx.y;
    const float* Lb = LSTM + (size_t)b * TE * EHD;
    const float* Ag = g_E + (size_t)b * TD * TE;

    float acc[2][8][4];
#pragma unroll
    for (int i = 0; i < 2; i++)
#pragma unroll
        for (int j = 0; j < 8; j++)
#pragma unroll
            for (int k = 0; k < 4; k++) acc[i][j][k] = 0.f;

    auto issue = [&](int kt) {
        uint32_t base = smb + (kt % 3) * AV_STG;
#pragma unroll
        for (int r = 0; r < 4; r++) {   // A: 128 rows x 8 chunks
            int lin = tid + 256 * r;
            int row = lin >> 3, q = lin & 7;
            cp16(base + (row * 36 + 4 * q) * 4,
                 Ag + (size_t)row * TE + kt * 32 + 4 * q);
        }
#pragma unroll
        for (int r = 0; r < 4; r++) {   // B: 32 k x 32 chunks (k-major)
            int lin = tid + 256 * r;
            int kk = lin >> 5, cq = lin & 31;
            cp16(base + 18432 + (kk * 136 + 4 * cq) * 4,
                 Lb + (size_t)(kt * 32 + kk) * EHD + e0 + 4 * cq);
        }
    };
    auto comp = [&](int kt) {
        const float* A = sm + (kt % 3) * (AV_STG / 4);
        const float* B = A + 4608;
#pragma unroll
        for (int ks = 0; ks < 4; ks++) {
            uint32_t af[2][4];
#pragma unroll
            for (int mt = 0; mt < 2; mt++) {
                const float* p = A + (wm * 32 + mt * 16 + g) * 36 + ks * 8 + t;
                af[mt][0] = __float_as_uint(p[0]);
                af[mt][1] = __float_as_uint(p[8 * 36]);
                af[mt][2] = __float_as_uint(p[4]);
                af[mt][3] = __float_as_uint(p[8 * 36 + 4]);
            }
            int kb = ks * 8 + t;
#pragma unroll
            for (int nt = 0; nt < 8; nt++) {
                int c0 = wn * 64 + nt * 8 + g;
                uint32_t bf[2] = {__float_as_uint(B[kb * 136 + c0]),
                                  __float_as_uint(B[(kb + 4) * 136 + c0])};
                mma_tf32(acc[0][nt], af[0], bf);
                mma_tf32(acc[1][nt], af[1], bf);
            }
        }
    };

    issue(0); CP_COMMIT();
    issue(1); CP_COMMIT();
#pragma unroll 1
    for (int kt = 0; kt < 16; kt++) {
        CP_WAIT1();
        __syncthreads();
        if (kt + 2 < 16) { issue(kt + 2); CP_COMMIT(); }
        comp(kt);
    }

    // direct epilogue: each 4-lane quad writes full 32B sectors of g_ci
#pragma unroll
    for (int mt = 0; mt < 2; mt++) {
        int r0 = wm * 32 + mt * 16 + g;
#pragma unroll
        for (int nt = 0; nt < 8; nt++) {
            int c = e0 + wn * 64 + nt * 8 + 2 * t;
            *(float2*)(g_ci + (size_t)(b * TD + r0) * EHD + c) =
                make_float2(acc[mt][nt][0], acc[mt][nt][1]);
            *(float2*)(g_ci + (size_t)(b * TD + r0 + 8) * EHD + c) =
                make_float2(acc[mt][nt][2], acc[mt][nt][3]);
        }
    }
}

// ======== K7: gates GEMM, N=256 tile, mma.sync tf32 + cp.async + LSTM cell ===
#define NTK 20
#define GB_STG 55296   // A 128x36 f32 (18432) + B 256x36 f32 (36864)
#define SSTG2 260
#define SMEMG (3 * GB_STG)   // 165888
__global__ void __launch_bounds__(256) k_gates_mma(const float* __restrict__ m_i,
                                                   float* __restrict__ out) {
    extern __shared__ float sm[];
    uint32_t smb = smem_u32(sm);
    int tid = threadIdx.x, lane = tid & 31, wid = tid >> 5;
    int g = lane >> 2, t = lane & 3;
    int wm = wid >> 1, wn = wid & 1;   // 4 M-tiles x 2 N-tiles(128)
    int b = blockIdx.x, m0 = b * 128, d0 = blockIdx.y * 64;

    float acc[2][16][4];
#pragma unroll
    for (int i = 0; i < 2; i++)
#pragma unroll
        for (int j = 0; j < 16; j++)
#pragma unroll
            for (int k = 0; k < 4; k++) acc[i][j][k] = 0.f;

    auto issue = [&](int kt) {
        uint32_t base = smb + (kt % 3) * GB_STG;
#pragma unroll
        for (int r = 0; r < 4; r++) {   // A: 128 rows x 8 chunks
            int lin = tid + 256 * r;
            int row = lin >> 3, q = lin & 7;
            const float* src = (kt < 16)
                ? g_ci + (size_t)(m0 + row) * EHD + kt * 32 + 4 * q
                : g_cp2 + b * 128 + (kt - 16) * 32 + 4 * q;
            cp16(base + (row * 36 + 4 * q) * 4, src);
        }
#pragma unroll
        for (int r = 0; r < 8; r++) {   // B: 256 cols x 8 chunks (padded g_Wp)
            int lin = tid + 256 * r;
            int c = lin >> 3, q = lin & 7;
            int n = ((c >> 6) << 9) + d0 + (c & 63);
            cp16(base + 18432 + (c * 36 + 4 * q) * 4,
                 g_Wp + (size_t)n * KWP + kt * 32 + 4 * q);
        }
    };
    auto comp = [&](int kt) {
        const float* A = sm + (kt % 3) * (GB_STG / 4);
        const float* B = A + 4608;
#pragma unroll
        for (int ks = 0; ks < 4; ks++) {
            uint32_t af[2][4];
#pragma unroll
            for (int mt = 0; mt < 2; mt++) {
                const float* p = A + (wm * 32 + mt * 16 + g) * 36 + ks * 8 + t;
                af[mt][0] = __float_as_uint(p[0]);
                af[mt][1] = __float_as_uint(p[8 * 36]);
                af[mt][2] = __float_as_uint(p[4]);
                af[mt][3] = __float_as_uint(p[8 * 36 + 4]);
            }
#pragma unroll
            for (int nt = 0; nt < 16; nt++) {
                const float* q2 = B + (wn * 128 + nt * 8 + g) * 36 + ks * 8 + t;
                uint32_t bf[2] = {__float_as_uint(q2[0]), __float_as_uint(q2[4])};
                mma_tf32(acc[0][nt], af[0], bf);
                mma_tf32(acc[1][nt], af[1], bf);
            }
        }
    };

    issue(0); CP_COMMIT();
    issue(1); CP_COMMIT();
#pragma unroll 1
    for (int kt = 0; kt < NTK; kt++) {
        CP_WAIT1();
        __syncthreads();
        if (kt + 2 < NTK) { issue(kt + 2); CP_COMMIT(); }
        comp(kt);
    }
    __syncthreads();

    // stage 128x256 accum tile, stride 260
    float* stg = sm;
#pragma unroll
    for (int mt = 0; mt < 2; mt++) {
        int r0 = wm * 32 + mt * 16 + g;
#pragma unroll
        for (int nt = 0; nt < 16; nt++) {
            int c0 = wn * 128 + nt * 8 + 2 * t;
            stg[r0 * SSTG2 + c0]           = acc[mt][nt][0];
            stg[r0 * SSTG2 + c0 + 1]       = acc[mt][nt][1];
            stg[(r0 + 8) * SSTG2 + c0]     = acc[mt][nt][2];
            stg[(r0 + 8) * SSTG2 + c0 + 1] = acc[mt][nt][3];
        }
    }
    __syncthreads();
    int r = tid >> 1, h = tid & 1;
    const float* shp = g_sh + b * 4 * DHD;
    const float* mip = m_i + b * DHD;
#pragma unroll
    for (int j = 0; j < 32; j++) {
        int dd = h * 32 + j;
        int d = d0 + dd;
        float ig = stg[r * SSTG2 + dd]       + shp[d];
        float fg = stg[r * SSTG2 + 64 + dd]  + shp[DHD + d];
        float gg = stg[r * SSTG2 + 128 + dd] + shp[2 * DHD + d];
        float og = stg[r * SSTG2 + 192 + dd] + shp[3 * DHD + d];
        float cnew = sigm(fg) * mip[d] + sigm(ig) * tanhf(gg);
        out[(size_t)(m0 + r) * DHD + d] = sigm(og) * tanhf(cnew);
    }
}

// ---------------- launch -----------------------------------------------------
extern "C" void kernel_launch(void* const* d_in, const int* in_sizes, int n_in,
                              void* d_out, int out_size) {
    const float* LSTM  = (const float*)d_in[0];
    const float* CNNs  = (const float*)d_in[1];
    const float* Wa_w  = (const float*)d_in[2];
    const float* Wa_b  = (const float*)d_in[3];
    const float* Ua_w  = (const float*)d_in[4];
    const float* Ua_b  = (const float*)d_in[5];
    const float* va_w  = (const float*)d_in[6];
    const float* va_b  = (const float*)d_in[7];
    const float* phi_w = (const float*)d_in[8];
    const float* phi_b = (const float*)d_in[9];
    const float* Wih   = (const float*)d_in[10];
    const float* Whh   = (const float*)d_in[11];
    const float* bih   = (const float*)d_in[12];
    const float* bhh   = (const float*)d_in[13];
    const float* wij_w = (const float*)d_in[14];
    const float* wij_b = (const float*)d_in[15];
    const float* s_i   = (const float*)d_in[16];
    const float* m_i   = (const float*)d_in[17];
    float* out = (float*)d_out;

    static int smem_set = 0;
    if (!smem_set) {
        cudaFuncSetAttribute(k_gates_mma,  cudaFuncAttributeMaxDynamicSharedMemorySize, SMEMG);
        cudaFuncSetAttribute(k_escore_mma, cudaFuncAttributeMaxDynamicSharedMemorySize, 3 * ES_STG);
        cudaFuncSetAttribute(k_av_mma,     cudaFuncAttributeMaxDynamicSharedMemorySize, 3 * AV_STG);
        smem_set = 1;
    }

    k_packW<<<4 * DHD, 256>>>(Wih);
    k_phi<<<TE / PHI_E, 512>>>(phi_w, phi_b);
    k_prep<<<35, 256>>>(s_i, Wa_w, Wa_b, Whh, bhh, bih, wij_w, wij_b);
    k_cnn_ep<<<BB, KC * 32>>>(CNNs, wij_w);
    k_cnn_ap<<<1, BB * KC>>>();
    k_cnn_cp<<<BB, 128>>>(CNNs);
    k_escore_mma<<<dim3(8, 128), 256, 3 * ES_STG>>>(LSTM, Ua_w, Ua_b, va_w, va_b);
    k_softmax<<<BB * TD, 256>>>();
    k_av_mma<<<dim3(4, 128), 256, 3 * AV_STG>>>(LSTM);
    k_gates_mma<<<dim3(128, 8), 256, SMEMG>>>(m_i, out);
}

// round 16
// speedup vs baseline: 2.9542x; 1.0292x over previous
#include <cuda_runtime.h>
#include <cstdint>

#define BB 128
#define TE 512
#define TD 128
#define EHD 512
#define DHD 512
#define KC 7
#define CC 105
#define KW 617   // CC + DHD
#define KWP 640  // padded K for gates

// ---------------- scratch (device globals; no allocations allowed) -----------
__device__ float g_phi[TE * EHD];          // phi[t][e]
__device__ float g_Wa[BB * TD];            // Wa + Wa_b
__device__ float g_sh[BB * 4 * DHD];       // s_i@Whh.T + bhh + bih
__device__ float g_sdot[BB * KC];          // s_i@w_s.T + wij_b
__device__ float g_ep[BB * KC];            // tanh(ep)
__device__ float g_apv[BB * KC];           // exp(ep)/S
__device__ float g_cp2[BB * 128];          // c_p zero-padded to 128
__device__ float g_E[BB * TD * TE];        // scores -> softmax in place
__device__ float g_ci[BB * TD * EHD];      // attention output
__device__ float g_Wp[4 * DHD * KWP];      // Wih repacked, zero-padded rows (aligned)

__device__ __forceinline__ float sigm(float x) { return 1.f / (1.f + __expf(-x)); }
__device__ __forceinline__ uint32_t smem_u32(const void* p) {
    uint32_t a;
    asm("{ .reg .u64 t; cvta.to.shared.u64 t, %1; cvt.u32.u64 %0, t; }" : "=r"(a) : "l"(p));
    return a;
}
__device__ __forceinline__ void cp16(uint32_t dst, const void* src) {
    asm volatile("cp.async.ca.shared.global [%0], [%1], 16;" :: "r"(dst), "l"(src));
}
__device__ __forceinline__ void cp16z(uint32_t dst, const void* src, int sz) {
    asm volatile("cp.async.ca.shared.global [%0], [%1], 16, %2;" :: "r"(dst), "l"(src), "r"(sz));
}
#define CP_COMMIT() asm volatile("cp.async.commit_group;" ::: "memory")
#define CP_WAIT1()  asm volatile("cp.async.wait_group 1;"  ::: "memory")
__device__ __forceinline__ void mma_tf32(float* d, const uint32_t* a, const uint32_t* b) {
    asm volatile("mma.sync.aligned.m16n8k8.row.col.f32.tf32.tf32.f32 "
                 "{%0,%1,%2,%3}, {%4,%5,%6,%7}, {%8,%9}, {%0,%1,%2,%3};"
                 : "+f"(d[0]), "+f"(d[1]), "+f"(d[2]), "+f"(d[3])
                 : "r"(a[0]), "r"(a[1]), "r"(a[2]), "r"(a[3]), "r"(b[0]), "r"(b[1]));
}

// ---------------- K0: repack Wih rows 617 -> 640 (aligned, zero-padded) ------
__global__ void k_packW(const float* __restrict__ Wih) {
    int n = blockIdx.x;
    const float* src = Wih + (size_t)n * KW;
    float* dst = g_Wp + (size_t)n * KWP;
    for (int k = threadIdx.x; k < KWP; k += 256)
        dst[k] = (k < KW) ? src[k] : 0.f;
}

// ---------------- K1: phi scan, warp-per-column + coalesced transpose write --
#define PHI_E 16
__global__ void __launch_bounds__(512) k_phi(const float* __restrict__ phi_w,
                                             const float* __restrict__ phi_b) {
    __shared__ float smt[TE][PHI_E + 1];
    int wid = threadIdx.x >> 5, lane = threadIdx.x & 31;
    int e = blockIdx.x * PHI_E + wid;
    const float* src = phi_w + (size_t)e * TE;
    float pb = phi_b[e];
    float carry = 0.f;
#pragma unroll 1
    for (int i = 0; i < 16; i++) {
        int t = 32 * i + lane;
        float v = src[t];
        float x = v;
#pragma unroll
        for (int o = 1; o < 32; o <<= 1) {
            float y = __shfl_up_sync(0xffffffffu, x, o);
            if (lane >= o) x += y;
        }
        smt[t][wid] = pb + carry + x - v;   // exclusive prefix
        carry += __shfl_sync(0xffffffffu, x, 31);
    }
    __syncthreads();
    int e0 = blockIdx.x * PHI_E;
#pragma unroll 1
    for (int idx = threadIdx.x; idx < TE * PHI_E; idx += 512) {
        int t = idx >> 4, el = idx & 15;
        g_phi[t * EHD + e0 + el] = smt[t][el];
    }
}

// ---------------- K2: fused small GEMM: C = s_i @ W.T for [Wa_w; Whh; w_s] ---
#define N2 2183   // 128 + 2048 + 7
__global__ void k_prep(const float* __restrict__ s_i,
                       const float* __restrict__ Wa_w, const float* __restrict__ Wa_b,
                       const float* __restrict__ Whh,  const float* __restrict__ bhh,
                       const float* __restrict__ bih,
                       const float* __restrict__ wij_w, const float* __restrict__ wij_b) {
    __shared__ float As[128][33];
    __shared__ float Ws[64][33];
    int tid = threadIdx.x;
    int tx = tid & 15, ty = tid >> 4;
    int n0 = blockIdx.x * 64;
    float acc[8][4];
#pragma unroll
    for (int a = 0; a < 8; a++)
#pragma unroll
        for (int c = 0; c < 4; c++) acc[a][c] = 0.f;

    for (int k0 = 0; k0 < DHD; k0 += 32) {
#pragma unroll
        for (int r = 0; r < 16; r++) {
            int lin = tid + 256 * r;
            int row = lin >> 5, kk = lin & 31;
            As[row][kk] = s_i[row * DHD + k0 + kk];
        }
#pragma unroll
        for (int r = 0; r < 8; r++) {
            int lin = tid + 256 * r;
            int col = lin >> 5, kk = lin & 31;
            int n = n0 + col, k = k0 + kk;
            float v = 0.f;
            if (n < TD)                 v = Wa_w[n * DHD + k];
            else if (n < TD + 4 * DHD)  v = Whh[(n - TD) * DHD + k];
            else if (n < N2)            v = wij_w[(n - TD - 4 * DHD) * KW + CC + k];
            Ws[col][kk] = v;
        }
        __syncthreads();
#pragma unroll
        for (int kk = 0; kk < 32; kk++) {
            float xv[8], wv[4];
#pragma unroll
            for (int jm = 0; jm < 8; jm++) xv[jm] = As[ty + 16 * jm][kk];
#pragma unroll
            for (int jn = 0; jn < 4; jn++) wv[jn] = Ws[tx + 16 * jn][kk];
#pragma unroll
            for (int jm = 0; jm < 8; jm++)
#pragma unroll
                for (int jn = 0; jn < 4; jn++) acc[jm][jn] += xv[jm] * wv[jn];
        }
        __syncthreads();
    }
#pragma unroll
    for (int jm = 0; jm < 8; jm++) {
        int m = ty + 16 * jm;
#pragma unroll
        for (int jn = 0; jn < 4; jn++) {
            int n = n0 + tx + 16 * jn;
            float v = acc[jm][jn];
            if (n < TD)                g_Wa[m * TD + n] = v + Wa_b[n];
            else if (n < TD + 4 * DHD) g_sh[m * 4 * DHD + (n - TD)] = v + bhh[n - TD] + bih[n - TD];
            else if (n < N2)           g_sdot[m * KC + (n - TD - 4 * DHD)] = v + wij_b[n - TD - 4 * DHD];
        }
    }
}

// ---------------- K3a/b/c: CNN path, parallelized ----------------------------
__global__ void k_cnn_ep(const float* __restrict__ CNNs, const float* __restrict__ wij_w) {
    int b = blockIdx.x;
    int wid = threadIdx.x >> 5, lane = threadIdx.x & 31;   // 7 warps, warp = k
    const float* crow = CNNs + (size_t)(b * KC + wid) * CC;
    const float* wrow = wij_w + (size_t)wid * KW;
    float acc = 0.f;
#pragma unroll 1
    for (int c = lane; c < CC; c += 32) acc += crow[c] * wrow[c];
#pragma unroll
    for (int o = 16; o; o >>= 1) acc += __shfl_xor_sync(0xffffffffu, acc, o);
    if (lane == 0) g_ep[b * KC + wid] = tanhf(acc + g_sdot[b * KC + wid]);
}
__global__ void k_cnn_ap() {
    __shared__ float red[28];
    __shared__ float Ssh;
    int tid = threadIdx.x;   // 896
    float e = g_ep[tid];
    float v = e;
#pragma unroll
    for (int o = 16; o; o >>= 1) v += __shfl_xor_sync(0xffffffffu, v, o);
    if ((tid & 31) == 0) red[tid >> 5] = v;
    __syncthreads();
    if (tid == 0) {
        float s = 0.f;
        for (int w = 0; w < 28; w++) s += red[w];
        Ssh = s;            // reference divides by sum of ep (not exp(ep))
    }
    __syncthreads();
    g_apv[tid] = __expf(e) / Ssh;
}
__global__ void k_cnn_cp(const float* __restrict__ CNNs) {
    int b = blockIdx.x, c = threadIdx.x;   // 128 threads
    __shared__ float ap[KC];
    if (c < KC) ap[c] = g_apv[b * KC + c];
    __syncthreads();
    float s = 0.f;
    if (c < CC) {
#pragma unroll
        for (int k = 0; k < KC; k++)
            s += ap[k] * CNNs[(size_t)(b * KC + k) * CC + c];
    }
    g_cp2[b * 128 + c] = s;
}

// ========== K4: banded score GEMM via mma.sync tf32 + 3-stage cp.async =======
#define ES_STG 36864   // bytes per stage: A 64x36 f32 (9216) + B 192x36 f32 (27648)
__global__ void __launch_bounds__(256) k_escore_mma(const float* __restrict__ LSTM,
                                                    const float* __restrict__ Ua_w,
                                                    const float* __restrict__ Ua_b,
                                                    const float* __restrict__ va_w,
                                                    const float* __restrict__ va_b) {
    extern __shared__ float sm[];
    uint32_t smb = smem_u32(sm);
    int tid = threadIdx.x, lane = tid & 31, wid = tid >> 5;
    int g = lane >> 2, t = lane & 3;
    int wm = wid & 1, wn = wid >> 1;           // 2 x 4 warp grid
    int t0 = blockIdx.x * 64, b = blockIdx.y;
    int s_lo = 321 - t0;
    const float* Lb = LSTM + (size_t)b * TE * EHD;

    float acc[2][6][4];
#pragma unroll
    for (int i = 0; i < 2; i++)
#pragma unroll
        for (int j = 0; j < 6; j++)
#pragma unroll
            for (int k = 0; k < 4; k++) acc[i][j][k] = 0.f;

    auto issueB = [&](int kt) {
        uint32_t base = smb + (kt % 3) * ES_STG + 9216;
#pragma unroll
        for (int r = 0; r < 6; r++) {
            int lin = tid + 256 * r;
            int c = lin >> 3, q = lin & 7;
            int s = s_lo + c;
            int sc = s < 0 ? 0 : (s > 511 ? 511 : s);
            cp16z(base + (c * 36 + 4 * q) * 4,
                  Ua_w + (size_t)sc * EHD + kt * 32 + 4 * q,
                  ((unsigned)s < 512u) ? 16 : 0);
        }
    };
    auto ldstA = [&](int kt) {
        float* A = sm + (kt % 3) * (ES_STG / 4);
#pragma unroll
        for (int r = 0; r < 2; r++) {
            int lin = tid + 256 * r;
            int row = lin >> 3, q = lin & 7;
            int off = (t0 + row) * EHD + kt * 32 + 4 * q;
            float4 p = *(const float4*)(g_phi + off);
            float4 l = *(const float4*)(Lb + off);
            float4 o = {p.x * l.x, p.y * l.y, p.z * l.z, p.w * l.w};
            *(float4*)(A + row * 36 + 4 * q) = o;
        }
    };
    auto comp = [&](int kt) {
        const float* A = sm + (kt % 3) * (ES_STG / 4);
        const float* B = A + 2304;
#pragma unroll
        for (int ks = 0; ks < 4; ks++) {
            uint32_t af[2][4];
#pragma unroll
            for (int mt = 0; mt < 2; mt++) {
                const float* p = A + (wm * 32 + mt * 16 + g) * 36 + ks * 8 + t;
                af[mt][0] = __float_as_uint(p[0]);
                af[mt][1] = __float_as_uint(p[8 * 36]);
                af[mt][2] = __float_as_uint(p[4]);
                af[mt][3] = __float_as_uint(p[8 * 36 + 4]);
            }
#pragma unroll
            for (int nt = 0; nt < 6; nt++) {
                const float* q2 = B + (wn * 48 + nt * 8 + g) * 36 + ks * 8 + t;
                uint32_t bf[2] = {__float_as_uint(q2[0]), __float_as_uint(q2[4])};
                mma_tf32(acc[0][nt], af[0], bf);
                mma_tf32(acc[1][nt], af[1], bf);
            }
        }
    };

    issueB(0); CP_COMMIT(); ldstA(0);
    issueB(1); CP_COMMIT(); ldstA(1);
#pragma unroll 1
    for (int kt = 0; kt < 16; kt++) {
        CP_WAIT1();
        __syncthreads();
        if (kt + 2 < 16) { issueB(kt + 2); CP_COMMIT(); ldstA(kt + 2); }
        comp(kt);
    }
    __syncthreads();

    // stage C [64][192] to smem (stride 196), then band epilogue
    float* stg = sm;
#pragma unroll
    for (int mt = 0; mt < 2; mt++) {
        int r0 = wm * 32 + mt * 16 + g;
#pragma unroll
        for (int nt = 0; nt < 6; nt++) {
            int c0 = wn * 48 + nt * 8 + 2 * t;
            stg[r0 * 196 + c0]           = acc[mt][nt][0];
            stg[r0 * 196 + c0 + 1]       = acc[mt][nt][1];
            stg[(r0 + 8) * 196 + c0]     = acc[mt][nt][2];
            stg[(r0 + 8) * 196 + c0 + 1] = acc[mt][nt][3];
        }
    }
    __syncthreads();
    float vb = va_b[0];
#pragma unroll 1
    for (int r = 0; r < 32; r++) {
        int lin = tid + 256 * r;
        int tt = lin & 63, ii = lin >> 6;
        int sp = ii - tt + 63;
        int s = s_lo + sp;
        int jc = s + 128;
        float ev;
        if (s >= 0) ev = tanhf(stg[tt * 196 + sp] + Ua_b[s]) * va_w[jc] + vb;
        else        ev = tanhf(g_Wa[b * TD + jc]) * va_w[jc] + vb;
        g_E[((size_t)(b * TD + ii)) * TE + t0 + tt] = ev;
    }
}

// ---------------- K5: row softmax over t (float4, 128 threads/row) -----------
__global__ void __launch_bounds__(128) k_softmax() {
    int row = blockIdx.x;
    float4* p = (float4*)(g_E + (size_t)row * TE);
    int tid = threadIdx.x;             // 128: one float4 each
    int lane = tid & 31, wid = tid >> 5;
    __shared__ float red[4], red2[4];
    float4 v = p[tid];
    float m = fmaxf(fmaxf(v.x, v.y), fmaxf(v.z, v.w));
#pragma unroll
    for (int o = 16; o; o >>= 1) m = fmaxf(m, __shfl_xor_sync(0xffffffffu, m, o));
    if (lane == 0) red[wid] = m;
    __syncthreads();
    m = fmaxf(fmaxf(red[0], red[1]), fmaxf(red[2], red[3]));
    float4 e;
    e.x = __expf(v.x - m); e.y = __expf(v.y - m);
    e.z = __expf(v.z - m); e.w = __expf(v.w - m);
    float s = (e.x + e.y) + (e.z + e.w);
#pragma unroll
    for (int o = 16; o; o >>= 1) s += __shfl_xor_sync(0xffffffffu, s, o);
    if (lane == 0) red2[wid] = s;
    __syncthreads();
    float inv = 1.f / (((red2[0] + red2[1]) + (red2[2] + red2[3])));
    e.x *= inv; e.y *= inv; e.z *= inv; e.w *= inv;
    p[tid] = e;
}

// ========== K6: c_i[b] = a[b] @ LSTM[b] via mma tf32 + 3-stage cp.async ======
#define AV_STG 35840   // A 128x36 f32 (18432) + B 32x136 f32 (17408)
__global__ void __launch_bounds__(256) k_av_mma(const float* __restrict__ LSTM) {
    extern __shared__ float sm[];
    uint32_t smb = smem_u32(sm);
    int tid = threadIdx.x, lane = tid & 31, wid = tid >> 5;
    int g = lane >> 2, t = lane & 3;
    int wm = wid >> 1, wn = wid & 1;   // 4 x 2 warp grid
    int e0 = blockIdx.x * 128, b = blockIdx.y;
    const float* Lb = LSTM + (size_t)b * TE * EHD;
    const float* Ag = g_E + (size_t)b * TD * TE;

    float acc[2][8][4];
#pragma unroll
    for (int i = 0; i < 2; i++)
#pragma unroll
        for (int j = 0; j < 8; j++)
#pragma unroll
            for (int k = 0; k < 4; k++) acc[i][j][k] = 0.f;

    auto issue = [&](int kt) {
        uint32_t base = smb + (kt % 3) * AV_STG;
#pragma unroll
        for (int r = 0; r < 4; r++) {   // A: 128 rows x 8 chunks
            int lin = tid + 256 * r;
            int row = lin >> 3, q = lin & 7;
            cp16(base + (row * 36 + 4 * q) * 4,
                 Ag + (size_t)row * TE + kt * 32 + 4 * q);
        }
#pragma unroll
        for (int r = 0; r < 4; r++) {   // B: 32 k x 32 chunks (k-major)
            int lin = tid + 256 * r;
            int kk = lin >> 5, cq = lin & 31;
            cp16(base + 18432 + (kk * 136 + 4 * cq) * 4,
                 Lb + (size_t)(kt * 32 + kk) * EHD + e0 + 4 * cq);
        }
    };
    auto comp = [&](int kt) {
        const float* A = sm + (kt % 3) * (AV_STG / 4);
        const float* B = A + 4608;
#pragma unroll
        for (int ks = 0; ks < 4; ks++) {
            uint32_t af[2][4];
#pragma unroll
            for (int mt = 0; mt < 2; mt++) {
                const float* p = A + (wm * 32 + mt * 16 + g) * 36 + ks * 8 + t;
                af[mt][0] = __float_as_uint(p[0]);
                af[mt][1] = __float_as_uint(p[8 * 36]);
                af[mt][2] = __float_as_uint(p[4]);
                af[mt][3] = __float_as_uint(p[8 * 36 + 4]);
            }
            int kb = ks * 8 + t;
#pragma unroll
            for (int nt = 0; nt < 8; nt++) {
                int c0 = wn * 64 + nt * 8 + g;
                uint32_t bf[2] = {__float_as_uint(B[kb * 136 + c0]),
                                  __float_as_uint(B[(kb + 4) * 136 + c0])};
                mma_tf32(acc[0][nt], af[0], bf);
                mma_tf32(acc[1][nt], af[1], bf);
            }
        }
    };

    issue(0); CP_COMMIT();
    issue(1); CP_COMMIT();
#pragma unroll 1
    for (int kt = 0; kt < 16; kt++) {
        CP_WAIT1();
        __syncthreads();
        if (kt + 2 < 16) { issue(kt + 2); CP_COMMIT(); }
        comp(kt);
    }

    // direct epilogue: each 4-lane quad writes full 32B sectors of g_ci
#pragma unroll
    for (int mt = 0; mt < 2; mt++) {
        int r0 = wm * 32 + mt * 16 + g;
#pragma unroll
        for (int nt = 0; nt < 8; nt++) {
            int c = e0 + wn * 64 + nt * 8 + 2 * t;
            *(float2*)(g_ci + (size_t)(b * TD + r0) * EHD + c) =
                make_float2(acc[mt][nt][0], acc[mt][nt][1]);
            *(float2*)(g_ci + (size_t)(b * TD + r0 + 8) * EHD + c) =
                make_float2(acc[mt][nt][2], acc[mt][nt][3]);
        }
    }
}

// ======== K7: gates GEMM N=128, mma tf32, 3-stage cp.async + LSTM cell =======
#define NTK 20
#define GA_STG 36864   // A 128x36 f32 (18432) + B 128x36 f32 (18432)
#define SSTG 132
#define SMEMG (3 * GA_STG)
__global__ void __launch_bounds__(256) k_gates_mma(const float* __restrict__ m_i,
                                                   float* __restrict__ out) {
    extern __shared__ float sm[];
    uint32_t smb = smem_u32(sm);
    int tid = threadIdx.x, lane = tid & 31, wid = tid >> 5;
    int g = lane >> 2, t = lane & 3;
    int wm = wid >> 1, wn = wid & 1;
    int b = blockIdx.x, m0 = b * 128, d0 = blockIdx.y * 32;

    float acc[2][8][4];
#pragma unroll
    for (int i = 0; i < 2; i++)
#pragma unroll
        for (int j = 0; j < 8; j++)
#pragma unroll
            for (int k = 0; k < 4; k++) acc[i][j][k] = 0.f;

    auto issue = [&](int kt) {
        uint32_t base = smb + (kt % 3) * GA_STG;
#pragma unroll
        for (int r = 0; r < 4; r++) {   // A: 128 rows x 8 chunks
            int lin = tid + 256 * r;
            int row = lin >> 3, q = lin & 7;
            const float* src = (kt < 16)
                ? g_ci + (size_t)(m0 + row) * EHD + kt * 32 + 4 * q
                : g_cp2 + b * 128 + (kt - 16) * 32 + 4 * q;
            cp16(base + (row * 36 + 4 * q) * 4, src);
        }
#pragma unroll
        for (int r = 0; r < 4; r++) {   // B: 128 cols x 8 chunks (padded g_Wp)
            int lin = tid + 256 * r;
            int c = lin >> 3, q = lin & 7;
            int n = ((c >> 5) << 9) + d0 + (c & 31);
            cp16(base + 18432 + (c * 36 + 4 * q) * 4,
                 g_Wp + (size_t)n * KWP + kt * 32 + 4 * q);
        }
    };
    auto comp = [&](int kt) {
        const float* A = sm + (kt % 3) * (GA_STG / 4);
        const float* B = A + 4608;
#pragma unroll
        for (int ks = 0; ks < 4; ks++) {
            uint32_t af[2][4];
#pragma unroll
            for (int mt = 0; mt < 2; mt++) {
                const float* p = A + (wm * 32 + mt * 16 + g) * 36 + ks * 8 + t;
                af[mt][0] = __float_as_uint(p[0]);
                af[mt][1] = __float_as_uint(p[8 * 36]);
                af[mt][2] = __float_as_uint(p[4]);
                af[mt][3] = __float_as_uint(p[8 * 36 + 4]);
            }
#pragma unroll
            for (int nt = 0; nt < 8; nt++) {
                const float* q2 = B + (wn * 64 + nt * 8 + g) * 36 + ks * 8 + t;
                uint32_t bf[2] = {__float_as_uint(q2[0]), __float_as_uint(q2[4])};
                mma_tf32(acc[0][nt], af[0], bf);
                mma_tf32(acc[1][nt], af[1], bf);
            }
        }
    };

    issue(0); CP_COMMIT();
    issue(1); CP_COMMIT();
#pragma unroll 1
    for (int kt = 0; kt < NTK; kt++) {
        CP_WAIT1();
        __syncthreads();
        if (kt + 2 < NTK) { issue(kt + 2); CP_COMMIT(); }
        comp(kt);
    }
    __syncthreads();

    float* stg = sm;
#pragma unroll
    for (int mt = 0; mt < 2; mt++) {
        int r0 = wm * 32 + mt * 16 + g;
#pragma unroll
        for (int nt = 0; nt < 8; nt++) {
            int c0 = wn * 64 + nt * 8 + 2 * t;
            stg[r0 * SSTG + c0]           = acc[mt][nt][0];
            stg[r0 * SSTG + c0 + 1]       = acc[mt][nt][1];
            stg[(r0 + 8) * SSTG + c0]     = acc[mt][nt][2];
            stg[(r0 + 8) * SSTG + c0 + 1] = acc[mt][nt][3];
        }
    }
    __syncthreads();
    int r = tid >> 1, h = tid & 1;
    const float* shp = g_sh + b * 4 * DHD;
    const float* mip = m_i + b * DHD;
#pragma unroll
    for (int j = 0; j < 16; j++) {
        int dd = h * 16 + j;
        int d = d0 + dd;
        float ig = stg[r * SSTG + dd]      + shp[d];
        float fg = stg[r * SSTG + 32 + dd] + shp[DHD + d];
        float gg = stg[r * SSTG + 64 + dd] + shp[2 * DHD + d];
        float og = stg[r * SSTG + 96 + dd] + shp[3 * DHD + d];
        float cnew = sigm(fg) * mip[d] + sigm(ig) * tanhf(gg);
        out[(size_t)(m0 + r) * DHD + d] = sigm(og) * tanhf(cnew);
    }
}

// ---------------- launch -----------------------------------------------------
extern "C" void kernel_launch(void* const* d_in, const int* in_sizes, int n_in,
                              void* d_out, int out_size) {
    const float* LSTM  = (const float*)d_in[0];
    const float* CNNs  = (const float*)d_in[1];
    const float* Wa_w  = (const float*)d_in[2];
    const float* Wa_b  = (const float*)d_in[3];
    const float* Ua_w  = (const float*)d_in[4];
    const float* Ua_b  = (const float*)d_in[5];
    const float* va_w  = (const float*)d_in[6];
    const float* va_b  = (const float*)d_in[7];
    const float* phi_w = (const float*)d_in[8];
    const float* phi_b = (const float*)d_in[9];
    const float* Wih   = (const float*)d_in[10];
    const float* Whh   = (const float*)d_in[11];
    const float* bih   = (const float*)d_in[12];
    const float* bhh   = (const float*)d_in[13];
    const float* wij_w = (const float*)d_in[14];
    const float* wij_b = (const float*)d_in[15];
    const float* s_i   = (const float*)d_in[16];
    const float* m_i   = (const float*)d_in[17];
    float* out = (float*)d_out;

    static int smem_set = 0;
    if (!smem_set) {
        cudaFuncSetAttribute(k_gates_mma,  cudaFuncAttributeMaxDynamicSharedMemorySize, SMEMG);
        cudaFuncSetAttribute(k_escore_mma, cudaFuncAttributeMaxDynamicSharedMemorySize, 3 * ES_STG);
        cudaFuncSetAttribute(k_av_mma,     cudaFuncAttributeMaxDynamicSharedMemorySize, 3 * AV_STG);
        smem_set = 1;
    }

    k_packW<<<4 * DHD, 256>>>(Wih);
    k_phi<<<TE / PHI_E, 512>>>(phi_w, phi_b);
    k_prep<<<35, 256>>>(s_i, Wa_w, Wa_b, Whh, bhh, bih, wij_w, wij_b);
    k_cnn_ep<<<BB, KC * 32>>>(CNNs, wij_w);
    k_cnn_ap<<<1, BB * KC>>>();
    k_cnn_cp<<<BB, 128>>>(CNNs);
    k_escore_mma<<<dim3(8, 128), 256, 3 * ES_STG>>>(LSTM, Ua_w, Ua_b, va_w, va_b);
    k_softmax<<<BB * TD, 128>>>();
    k_av_mma<<<dim3(4, 128), 256, 3 * AV_STG>>>(LSTM);
    k_gates_mma<<<dim3(128, 16), 256, SMEMG>>>(m_i, out);
}